// round 1
// baseline (speedup 1.0000x reference)
#include <cuda_runtime.h>
#include <math.h>

#define D_MODEL 2048
#define NUM_HEADS 16
#define HEAD_DIM 128
#define BATCH 2
#define SEQ 2048
#define MROWS (BATCH*SEQ)

// -------- scratch (no allocations allowed) --------
__device__ float g_q[(size_t)BATCH*NUM_HEADS*SEQ*HEAD_DIM];
__device__ float g_k[(size_t)BATCH*NUM_HEADS*SEQ*HEAD_DIM];
__device__ float g_v[(size_t)BATCH*NUM_HEADS*SEQ*HEAD_DIM];
__device__ float g_ctx[(size_t)MROWS*D_MODEL];

// ============================================================
// GEMM: C[m][n] = sum_k A[m][k] * W[n][k] + bias[n]
// A: [M,K] row-major, W: [N,K] row-major (torch Linear weight)
// bhsd=1: scatter into [B,H,S,Dh];  bhsd=0: write [m][n] row-major
// 128x128 tile, BK=16, 256 threads, 8x8 microtile
// ============================================================
__global__ __launch_bounds__(256, 2)
void gemm_bt(const float* __restrict__ A, const float* __restrict__ W,
             const float* __restrict__ bias, float* __restrict__ out,
             int M, int N, int K, int bhsd)
{
    __shared__ float As[16][132];
    __shared__ float Bs[16][132];

    const int tid = threadIdx.x;
    const int m0 = blockIdx.y * 128;
    const int n0 = blockIdx.x * 128;
    const int rbase = (tid >> 4) * 8;
    const int cbase = (tid & 15) * 8;

    float acc[8][8];
#pragma unroll
    for (int i = 0; i < 8; i++)
#pragma unroll
        for (int j = 0; j < 8; j++) acc[i][j] = 0.f;

    for (int k0 = 0; k0 < K; k0 += 16) {
        // load tiles: 128 rows x 16 k each = 512 float4
#pragma unroll
        for (int t = tid; t < 512; t += 256) {
            const int row = t >> 2;
            const int kq = (t & 3) << 2;
            float4 av = *(const float4*)&A[(size_t)(m0 + row) * K + k0 + kq];
            As[kq + 0][row] = av.x; As[kq + 1][row] = av.y;
            As[kq + 2][row] = av.z; As[kq + 3][row] = av.w;
            float4 bv = *(const float4*)&W[(size_t)(n0 + row) * K + k0 + kq];
            Bs[kq + 0][row] = bv.x; Bs[kq + 1][row] = bv.y;
            Bs[kq + 2][row] = bv.z; Bs[kq + 3][row] = bv.w;
        }
        __syncthreads();

#pragma unroll
        for (int kk = 0; kk < 16; kk++) {
            float4 a0 = *(const float4*)&As[kk][rbase];
            float4 a1 = *(const float4*)&As[kk][rbase + 4];
            float4 b0 = *(const float4*)&Bs[kk][cbase];
            float4 b1 = *(const float4*)&Bs[kk][cbase + 4];
            float a[8] = {a0.x, a0.y, a0.z, a0.w, a1.x, a1.y, a1.z, a1.w};
            float b[8] = {b0.x, b0.y, b0.z, b0.w, b1.x, b1.y, b1.z, b1.w};
#pragma unroll
            for (int i = 0; i < 8; i++)
#pragma unroll
                for (int j = 0; j < 8; j++)
                    acc[i][j] += a[i] * b[j];
        }
        __syncthreads();
    }

    // epilogue
    float4 bb0 = *(const float4*)&bias[n0 + cbase];
    float4 bb1 = *(const float4*)&bias[n0 + cbase + 4];
    float bv[8] = {bb0.x, bb0.y, bb0.z, bb0.w, bb1.x, bb1.y, bb1.z, bb1.w};

    if (!bhsd) {
#pragma unroll
        for (int i = 0; i < 8; i++) {
            const int m = m0 + rbase + i;
            float4 o0, o1;
            o0.x = acc[i][0] + bv[0]; o0.y = acc[i][1] + bv[1];
            o0.z = acc[i][2] + bv[2]; o0.w = acc[i][3] + bv[3];
            o1.x = acc[i][4] + bv[4]; o1.y = acc[i][5] + bv[5];
            o1.z = acc[i][6] + bv[6]; o1.w = acc[i][7] + bv[7];
            float* dst = &out[(size_t)m * N + n0 + cbase];
            *(float4*)dst = o0;
            *(float4*)(dst + 4) = o1;
        }
    } else {
        // n range [n0+cbase, n0+cbase+8) lies within one head (cbase mult of 8)
        const int h = (n0 + cbase) >> 7;
        const int d0 = (n0 + cbase) & 127;
#pragma unroll
        for (int i = 0; i < 8; i++) {
            const int m = m0 + rbase + i;
            const int b = m >> 11;          // /SEQ
            const int s = m & 2047;         // %SEQ
            float4 o0, o1;
            o0.x = acc[i][0] + bv[0]; o0.y = acc[i][1] + bv[1];
            o0.z = acc[i][2] + bv[2]; o0.w = acc[i][3] + bv[3];
            o1.x = acc[i][4] + bv[4]; o1.y = acc[i][5] + bv[5];
            o1.z = acc[i][6] + bv[6]; o1.w = acc[i][7] + bv[7];
            float* dst = &out[(((size_t)(b * NUM_HEADS + h)) * SEQ + s) * HEAD_DIM + d0];
            *(float4*)dst = o0;
            *(float4*)(dst + 4) = o1;
        }
    }
}

// ============================================================
// Flash attention: per (bh, 64-query tile), loop 64-key tiles.
// Q/K stored transposed in smem ([d][row]) for conflict-free
// float4 microtile loads. Online softmax, O in registers.
// ============================================================
#define BQ 64
#define BKV 64
#define QST_LD 68
#define KST_LD 68
#define VS_LD 132
#define PS_LD 65
#define OFF_KST (128*QST_LD)
#define OFF_VS  (OFF_KST + 128*KST_LD)
#define OFF_PS  (OFF_VS + BKV*VS_LD)
#define OFF_M   (OFF_PS + BQ*PS_LD)
#define OFF_L   (OFF_M + BQ)
#define OFF_C   (OFF_L + BQ)
#define SMEM_FLOATS (OFF_C + BQ)

__global__ __launch_bounds__(256)
void attn_kernel(const float* __restrict__ Q, const float* __restrict__ Kg,
                 const float* __restrict__ Vg, float* __restrict__ ctx)
{
    extern __shared__ float sm[];
    float* Qst  = sm;
    float* Kst  = sm + OFF_KST;
    float* Vs   = sm + OFF_VS;
    float* Ps   = sm + OFF_PS;
    float* rowm = sm + OFF_M;
    float* rowl = sm + OFF_L;
    float* rowc = sm + OFF_C;

    const int tid = threadIdx.x;
    const int bh = blockIdx.y;
    const int q0 = blockIdx.x * BQ;
    const size_t base = (size_t)bh * SEQ * HEAD_DIM;
    const float* Qp = Q + base;
    const float* Kp = Kg + base;
    const float* Vp = Vg + base;

    const int ty = tid >> 4;   // 0..15
    const int tx = tid & 15;   // 0..15

    // load Q tile transposed: Qst[d][r]
    for (int t = tid; t < BQ * 32; t += 256) {
        const int r = t >> 5;
        const int dq = (t & 31) << 2;
        float4 q4 = *(const float4*)&Qp[(size_t)(q0 + r) * HEAD_DIM + dq];
        Qst[(dq + 0) * QST_LD + r] = q4.x;
        Qst[(dq + 1) * QST_LD + r] = q4.y;
        Qst[(dq + 2) * QST_LD + r] = q4.z;
        Qst[(dq + 3) * QST_LD + r] = q4.w;
    }
    if (tid < BQ) { rowm[tid] = -1e30f; rowl[tid] = 0.f; }

    float o[4][8];
#pragma unroll
    for (int i = 0; i < 4; i++)
#pragma unroll
        for (int c = 0; c < 8; c++) o[i][c] = 0.f;

    __syncthreads();

    const float scale = 0.0883883476483184f;   // 1/sqrt(128)

    for (int kv0 = 0; kv0 < SEQ; kv0 += BKV) {
        // load K transposed + V row-major
        for (int t = tid; t < BKV * 32; t += 256) {
            const int r = t >> 5;
            const int dq = (t & 31) << 2;
            float4 k4 = *(const float4*)&Kp[(size_t)(kv0 + r) * HEAD_DIM + dq];
            Kst[(dq + 0) * KST_LD + r] = k4.x;
            Kst[(dq + 1) * KST_LD + r] = k4.y;
            Kst[(dq + 2) * KST_LD + r] = k4.z;
            Kst[(dq + 3) * KST_LD + r] = k4.w;
            float4 v4 = *(const float4*)&Vp[(size_t)(kv0 + r) * HEAD_DIM + dq];
            *(float4*)&Vs[r * VS_LD + dq] = v4;
        }
        __syncthreads();

        // S = Q K^T (4x4 per thread)
        float s[4][4];
#pragma unroll
        for (int i = 0; i < 4; i++)
#pragma unroll
            for (int j = 0; j < 4; j++) s[i][j] = 0.f;

#pragma unroll 4
        for (int d = 0; d < HEAD_DIM; d++) {
            float4 a = *(const float4*)&Qst[d * QST_LD + ty * 4];
            float4 b = *(const float4*)&Kst[d * KST_LD + tx * 4];
            float av[4] = {a.x, a.y, a.z, a.w};
            float bvv[4] = {b.x, b.y, b.z, b.w};
#pragma unroll
            for (int i = 0; i < 4; i++)
#pragma unroll
                for (int j = 0; j < 4; j++)
                    s[i][j] += av[i] * bvv[j];
        }
#pragma unroll
        for (int i = 0; i < 4; i++)
#pragma unroll
            for (int j = 0; j < 4; j++)
                Ps[(ty * 4 + i) * PS_LD + tx * 4 + j] = s[i][j] * scale;
        __syncthreads();

        // softmax stats: 4 threads per row
        {
            const int r = tid >> 2;
            const int part = tid & 3;
            float* prow = &Ps[r * PS_LD + part * 16];
            float mx = -1e30f;
#pragma unroll
            for (int c = 0; c < 16; c++) mx = fmaxf(mx, prow[c]);
            mx = fmaxf(mx, __shfl_xor_sync(0xffffffffu, mx, 1));
            mx = fmaxf(mx, __shfl_xor_sync(0xffffffffu, mx, 2));
            const float mold = rowm[r];
            const float mnew = fmaxf(mold, mx);
            float ssum = 0.f;
#pragma unroll
            for (int c = 0; c < 16; c++) {
                float e = __expf(prow[c] - mnew);
                prow[c] = e;
                ssum += e;
            }
            ssum += __shfl_xor_sync(0xffffffffu, ssum, 1);
            ssum += __shfl_xor_sync(0xffffffffu, ssum, 2);
            if (part == 0) {
                const float corr = __expf(mold - mnew);
                rowc[r] = corr;
                rowl[r] = rowl[r] * corr + ssum;
                rowm[r] = mnew;
            }
        }
        __syncthreads();

        // O = O*c + P V
        float ci[4];
#pragma unroll
        for (int i = 0; i < 4; i++) ci[i] = rowc[ty * 4 + i];
#pragma unroll
        for (int i = 0; i < 4; i++)
#pragma unroll
            for (int c = 0; c < 8; c++) o[i][c] *= ci[i];

#pragma unroll 4
        for (int j = 0; j < BKV; j++) {
            float p[4];
#pragma unroll
            for (int i = 0; i < 4; i++) p[i] = Ps[(ty * 4 + i) * PS_LD + j];
            float4 v0 = *(const float4*)&Vs[j * VS_LD + tx * 8];
            float4 v1 = *(const float4*)&Vs[j * VS_LD + tx * 8 + 4];
            float vv[8] = {v0.x, v0.y, v0.z, v0.w, v1.x, v1.y, v1.z, v1.w};
#pragma unroll
            for (int i = 0; i < 4; i++)
#pragma unroll
                for (int c = 0; c < 8; c++)
                    o[i][c] += p[i] * vv[c];
        }
        __syncthreads();
    }

    // write [B,S,D] context
    const int b = bh >> 4;
    const int h = bh & 15;
#pragma unroll
    for (int i = 0; i < 4; i++) {
        const float inv = 1.f / rowl[ty * 4 + i];
        const int srow = q0 + ty * 4 + i;
        float* dst = &ctx[((size_t)(b * SEQ + srow)) * D_MODEL + h * HEAD_DIM + tx * 8];
        float4 o0, o1;
        o0.x = o[i][0] * inv; o0.y = o[i][1] * inv;
        o0.z = o[i][2] * inv; o0.w = o[i][3] * inv;
        o1.x = o[i][4] * inv; o1.y = o[i][5] * inv;
        o1.z = o[i][6] * inv; o1.w = o[i][7] * inv;
        *(float4*)dst = o0;
        *(float4*)(dst + 4) = o1;
    }
}

// ============================================================
extern "C" void kernel_launch(void* const* d_in, const int* in_sizes, int n_in,
                              void* d_out, int out_size)
{
    const float* x  = (const float*)d_in[0];
    const float* wq = (const float*)d_in[1];
    const float* bq = (const float*)d_in[2];
    const float* wk = (const float*)d_in[3];
    const float* bk = (const float*)d_in[4];
    const float* wv = (const float*)d_in[5];
    const float* bv = (const float*)d_in[6];
    const float* wo = (const float*)d_in[7];
    const float* bo = (const float*)d_in[8];
    float* out = (float*)d_out;

    float *q, *k, *v, *ctx;
    cudaGetSymbolAddress((void**)&q, g_q);
    cudaGetSymbolAddress((void**)&k, g_k);
    cudaGetSymbolAddress((void**)&v, g_v);
    cudaGetSymbolAddress((void**)&ctx, g_ctx);

    const dim3 ggrid(D_MODEL / 128, MROWS / 128);

    gemm_bt<<<ggrid, 256>>>(x, wq, bq, q, MROWS, D_MODEL, D_MODEL, 1);
    gemm_bt<<<ggrid, 256>>>(x, wk, bk, k, MROWS, D_MODEL, D_MODEL, 1);
    gemm_bt<<<ggrid, 256>>>(x, wv, bv, v, MROWS, D_MODEL, D_MODEL, 1);

    const size_t smem = (size_t)SMEM_FLOATS * sizeof(float);
    cudaFuncSetAttribute(attn_kernel, cudaFuncAttributeMaxDynamicSharedMemorySize, (int)smem);
    attn_kernel<<<dim3(SEQ / BQ, BATCH * NUM_HEADS), 256, smem>>>(q, k, v, ctx);

    gemm_bt<<<ggrid, 256>>>(ctx, wo, bo, out, MROWS, D_MODEL, D_MODEL, 0);
}

// round 3
// speedup vs baseline: 1.4048x; 1.4048x over previous
#include <cuda_runtime.h>
#include <cuda_bf16.h>
#include <cstdint>
#include <math.h>

#define D_MODEL 2048
#define NUM_HEADS 16
#define HEAD_DIM 128
#define BATCH 2
#define SEQ 2048
#define MROWS (BATCH*SEQ)
#define GK 2048

// ---------------- scratch (static; no allocations allowed) ----------------
__device__ __align__(256) float g_q[(size_t)BATCH*NUM_HEADS*SEQ*HEAD_DIM];
__device__ __align__(256) float g_k[(size_t)BATCH*NUM_HEADS*SEQ*HEAD_DIM];
__device__ __align__(256) float g_v[(size_t)BATCH*NUM_HEADS*SEQ*HEAD_DIM];
__device__ __align__(256) float g_ctx[(size_t)MROWS*D_MODEL];
__device__ __align__(256) __nv_bfloat16 g_xh[(size_t)MROWS*D_MODEL];
__device__ __align__(256) __nv_bfloat16 g_xl[(size_t)MROWS*D_MODEL];
__device__ __align__(256) __nv_bfloat16 g_wh[4][(size_t)D_MODEL*D_MODEL];
__device__ __align__(256) __nv_bfloat16 g_wl[4][(size_t)D_MODEL*D_MODEL];
__device__ __align__(256) __nv_bfloat16 g_ch[(size_t)MROWS*D_MODEL];
__device__ __align__(256) __nv_bfloat16 g_cl[(size_t)MROWS*D_MODEL];

// ---------------- helpers ----------------
__device__ __forceinline__ uint32_t smem_to_u32(const void* p) {
    uint32_t a;
    asm("{ .reg .u64 t; cvta.to.shared.u64 t, %1; cvt.u32.u64 %0, t; }" : "=r"(a) : "l"(p));
    return a;
}
__device__ __forceinline__ void ldsm4(uint32_t* r, uint32_t addr) {
    asm volatile("ldmatrix.sync.aligned.m8n8.x4.shared.b16 {%0,%1,%2,%3}, [%4];"
                 : "=r"(r[0]), "=r"(r[1]), "=r"(r[2]), "=r"(r[3]) : "r"(addr));
}
__device__ __forceinline__ void ldsm2(uint32_t* r, uint32_t addr) {
    asm volatile("ldmatrix.sync.aligned.m8n8.x2.shared.b16 {%0,%1}, [%2];"
                 : "=r"(r[0]), "=r"(r[1]) : "r"(addr));
}
__device__ __forceinline__ void mma_bf16(float* c, const uint32_t* a, const uint32_t* b) {
    asm volatile(
        "mma.sync.aligned.m16n8k16.row.col.f32.bf16.bf16.f32 "
        "{%0,%1,%2,%3}, {%4,%5,%6,%7}, {%8,%9}, {%0,%1,%2,%3};"
        : "+f"(c[0]), "+f"(c[1]), "+f"(c[2]), "+f"(c[3])
        : "r"(a[0]), "r"(a[1]), "r"(a[2]), "r"(a[3]), "r"(b[0]), "r"(b[1]));
}
__device__ __forceinline__ void cp16(uint32_t saddr, const void* gaddr) {
    asm volatile("cp.async.cg.shared.global [%0], [%1], 16;" :: "r"(saddr), "l"(gaddr));
}
#define CP_COMMIT() asm volatile("cp.async.commit_group;")
#define CP_WAIT(n)  asm volatile("cp.async.wait_group %0;" :: "n"(n))

// ---------------- split fp32 -> bf16 hi/lo ----------------
__global__ __launch_bounds__(256)
void split_kernel(const float* __restrict__ in, __nv_bfloat16* __restrict__ hi,
                  __nv_bfloat16* __restrict__ lo, int n4)
{
    int i = blockIdx.x * blockDim.x + threadIdx.x;
    if (i >= n4) return;
    float4 v = ((const float4*)in)[i];
    __nv_bfloat16 h0 = __float2bfloat16(v.x);
    __nv_bfloat16 h1 = __float2bfloat16(v.y);
    __nv_bfloat16 h2 = __float2bfloat16(v.z);
    __nv_bfloat16 h3 = __float2bfloat16(v.w);
    __nv_bfloat16 l0 = __float2bfloat16(v.x - __bfloat162float(h0));
    __nv_bfloat16 l1 = __float2bfloat16(v.y - __bfloat162float(h1));
    __nv_bfloat16 l2 = __float2bfloat16(v.z - __bfloat162float(h2));
    __nv_bfloat16 l3 = __float2bfloat16(v.w - __bfloat162float(h3));
    __nv_bfloat162* hp = (__nv_bfloat162*)hi;
    __nv_bfloat162* lp = (__nv_bfloat162*)lo;
    hp[2 * i] = __nv_bfloat162(h0, h1);
    hp[2 * i + 1] = __nv_bfloat162(h2, h3);
    lp[2 * i] = __nv_bfloat162(l0, l1);
    lp[2 * i + 1] = __nv_bfloat162(l2, l3);
}

// ---------------- mma.sync split-bf16 GEMM: C = A @ W^T + bias ----------------
// A: [M,K] bf16 hi/lo; W: [N,K] bf16 hi/lo (both K-major).
// CTA tile 128x128, BK=32, 256 threads = 8 warps (2x4), warp tile 64x32.
// SMEM row stride 40 bf16 (80 B) -> 16B-aligned, conflict-free ldmatrix.
#define BKC 32
#define ROWB 80                 // bytes per smem row
#define TILE_BYTES (128*ROWB)   // 10240
#define BUFB (4*TILE_BYTES)     // Ah,Al,Bh,Bl = 40960
#define NCH (GK/BKC)            // 64

__device__ __forceinline__ void load_chunk(uint32_t sbase,
                                           const __nv_bfloat16* g0, const __nv_bfloat16* g1,
                                           const __nv_bfloat16* g2, const __nv_bfloat16* g3,
                                           int k0, int tid)
{
    const __nv_bfloat16* gp[4] = {g0, g1, g2, g3};
#pragma unroll
    for (int t = 0; t < 8; t++) {
        const int id = tid + t * 256;
        const int tile = id >> 9;
        const int idx = id & 511;
        const int row = idx >> 2;
        const int c = idx & 3;
        uint32_t sa = sbase + tile * TILE_BYTES + row * ROWB + c * 16;
        const __nv_bfloat16* ga = gp[tile] + (size_t)row * GK + k0 + c * 8;
        cp16(sa, ga);
    }
    CP_COMMIT();
}

__global__ __launch_bounds__(256, 1)
void gemm_tc(const __nv_bfloat16* __restrict__ Ah, const __nv_bfloat16* __restrict__ Al,
             const __nv_bfloat16* __restrict__ Wh, const __nv_bfloat16* __restrict__ Wl,
             const float* __restrict__ bias, float* __restrict__ out, int bhsd)
{
    extern __shared__ char smem[];
    const uint32_t sb = smem_to_u32(smem);
    const int tid = threadIdx.x;
    const int lane = tid & 31;
    const int wid = tid >> 5;
    const int wm = wid >> 2;        // 0..1
    const int wn = wid & 3;         // 0..3
    const int n0 = blockIdx.x * 128;
    const int m0 = blockIdx.y * 128;

    const __nv_bfloat16* a_h = Ah + (size_t)m0 * GK;
    const __nv_bfloat16* a_l = Al + (size_t)m0 * GK;
    const __nv_bfloat16* b_h = Wh + (size_t)n0 * GK;
    const __nv_bfloat16* b_l = Wl + (size_t)n0 * GK;

    float acc[4][4][4];
#pragma unroll
    for (int mi = 0; mi < 4; mi++)
#pragma unroll
        for (int ni = 0; ni < 4; ni++)
#pragma unroll
            for (int e = 0; e < 4; e++) acc[mi][ni][e] = 0.f;

    load_chunk(sb, a_h, a_l, b_h, b_l, 0, tid);

    for (int ch = 0; ch < NCH; ch++) {
        if (ch + 1 < NCH) {
            load_chunk(sb + ((ch + 1) & 1) * BUFB, a_h, a_l, b_h, b_l, (ch + 1) * BKC, tid);
            CP_WAIT(1);
        } else {
            CP_WAIT(0);
        }
        __syncthreads();

        const uint32_t base = sb + (ch & 1) * BUFB;
        const uint32_t aBaseH = base;
        const uint32_t aBaseL = base + TILE_BYTES;
        const uint32_t bBaseH = base + 2 * TILE_BYTES;
        const uint32_t bBaseL = base + 3 * TILE_BYTES;

#pragma unroll
        for (int kk = 0; kk < 2; kk++) {
            uint32_t ah[4][4], al[4][4], bh[4][2], bl[4][2];
            const int arow = wm * 64 + (lane & 15);
            const uint32_t aoff = ((lane >> 4) * 16) + kk * 32;
#pragma unroll
            for (int mi = 0; mi < 4; mi++) {
                ldsm4(ah[mi], aBaseH + (arow + mi * 16) * ROWB + aoff);
                ldsm4(al[mi], aBaseL + (arow + mi * 16) * ROWB + aoff);
            }
            const int brow = wn * 32 + (lane & 7);
            const uint32_t boff = (((lane >> 3) & 1) * 16) + kk * 32;
#pragma unroll
            for (int ni = 0; ni < 4; ni++) {
                ldsm2(bh[ni], bBaseH + (brow + ni * 8) * ROWB + boff);
                ldsm2(bl[ni], bBaseL + (brow + ni * 8) * ROWB + boff);
            }
#pragma unroll
            for (int mi = 0; mi < 4; mi++)
#pragma unroll
                for (int ni = 0; ni < 4; ni++) {
                    mma_bf16(acc[mi][ni], ah[mi], bh[ni]);
                    mma_bf16(acc[mi][ni], ah[mi], bl[ni]);
                    mma_bf16(acc[mi][ni], al[mi], bh[ni]);
                }
        }
        __syncthreads();
    }

    // epilogue: frag layout m16n8 -> lane r=lane>>2 rows {r, r+8}, cols {2c, 2c+1}
    const int r = lane >> 2;
    const int cp = (lane & 3) * 2;
    const int mbase = m0 + wm * 64;
    const int nbase = n0 + wn * 32;
#pragma unroll
    for (int mi = 0; mi < 4; mi++) {
#pragma unroll
        for (int ni = 0; ni < 4; ni++) {
            const int n_g = nbase + ni * 8 + cp;
            const float b0v = bias[n_g], b1v = bias[n_g + 1];
            const int m0g = mbase + mi * 16 + r;
            const int m1g = m0g + 8;
            float2 v0, v1;
            v0.x = acc[mi][ni][0] + b0v; v0.y = acc[mi][ni][1] + b1v;
            v1.x = acc[mi][ni][2] + b0v; v1.y = acc[mi][ni][3] + b1v;
            if (!bhsd) {
                *(float2*)&out[(size_t)m0g * D_MODEL + n_g] = v0;
                *(float2*)&out[(size_t)m1g * D_MODEL + n_g] = v1;
            } else {
                const int h = n0 >> 7;
                const int d = n_g & 127;
                const int b0i = m0g >> 11, s0 = m0g & 2047;
                const int b1i = m1g >> 11, s1 = m1g & 2047;
                *(float2*)&out[(((size_t)(b0i * NUM_HEADS + h) * SEQ + s0) * HEAD_DIM) + d] = v0;
                *(float2*)&out[(((size_t)(b1i * NUM_HEADS + h) * SEQ + s1) * HEAD_DIM) + d] = v1;
            }
        }
    }
}

// ============================================================
// Flash attention (fp32 SIMT, unchanged from round 1)
// ============================================================
#define BQ 64
#define BKV 64
#define QST_LD 68
#define KST_LD 68
#define VS_LD 132
#define PS_LD 65
#define OFF_KST (128*QST_LD)
#define OFF_VS  (OFF_KST + 128*KST_LD)
#define OFF_PS  (OFF_VS + BKV*VS_LD)
#define OFF_M   (OFF_PS + BQ*PS_LD)
#define OFF_L   (OFF_M + BQ)
#define OFF_C   (OFF_L + BQ)
#define SMEM_FLOATS (OFF_C + BQ)

__global__ __launch_bounds__(256)
void attn_kernel(const float* __restrict__ Q, const float* __restrict__ Kg,
                 const float* __restrict__ Vg, float* __restrict__ ctx)
{
    extern __shared__ float sm[];
    float* Qst  = sm;
    float* Kst  = sm + OFF_KST;
    float* Vs   = sm + OFF_VS;
    float* Ps   = sm + OFF_PS;
    float* rowm = sm + OFF_M;
    float* rowl = sm + OFF_L;
    float* rowc = sm + OFF_C;

    const int tid = threadIdx.x;
    const int bh = blockIdx.y;
    const int q0 = blockIdx.x * BQ;
    const size_t base = (size_t)bh * SEQ * HEAD_DIM;
    const float* Qp = Q + base;
    const float* Kp = Kg + base;
    const float* Vp = Vg + base;

    const int ty = tid >> 4;
    const int tx = tid & 15;

    for (int t = tid; t < BQ * 32; t += 256) {
        const int r = t >> 5;
        const int dq = (t & 31) << 2;
        float4 q4 = *(const float4*)&Qp[(size_t)(q0 + r) * HEAD_DIM + dq];
        Qst[(dq + 0) * QST_LD + r] = q4.x;
        Qst[(dq + 1) * QST_LD + r] = q4.y;
        Qst[(dq + 2) * QST_LD + r] = q4.z;
        Qst[(dq + 3) * QST_LD + r] = q4.w;
    }
    if (tid < BQ) { rowm[tid] = -1e30f; rowl[tid] = 0.f; }

    float o[4][8];
#pragma unroll
    for (int i = 0; i < 4; i++)
#pragma unroll
        for (int c = 0; c < 8; c++) o[i][c] = 0.f;

    __syncthreads();

    const float scale = 0.0883883476483184f;

    for (int kv0 = 0; kv0 < SEQ; kv0 += BKV) {
        for (int t = tid; t < BKV * 32; t += 256) {
            const int r = t >> 5;
            const int dq = (t & 31) << 2;
            float4 k4 = *(const float4*)&Kp[(size_t)(kv0 + r) * HEAD_DIM + dq];
            Kst[(dq + 0) * KST_LD + r] = k4.x;
            Kst[(dq + 1) * KST_LD + r] = k4.y;
            Kst[(dq + 2) * KST_LD + r] = k4.z;
            Kst[(dq + 3) * KST_LD + r] = k4.w;
            float4 v4 = *(const float4*)&Vp[(size_t)(kv0 + r) * HEAD_DIM + dq];
            *(float4*)&Vs[r * VS_LD + dq] = v4;
        }
        __syncthreads();

        float s[4][4];
#pragma unroll
        for (int i = 0; i < 4; i++)
#pragma unroll
            for (int j = 0; j < 4; j++) s[i][j] = 0.f;

#pragma unroll 4
        for (int d = 0; d < HEAD_DIM; d++) {
            float4 a = *(const float4*)&Qst[d * QST_LD + ty * 4];
            float4 b = *(const float4*)&Kst[d * KST_LD + tx * 4];
            float av[4] = {a.x, a.y, a.z, a.w};
            float bvv[4] = {b.x, b.y, b.z, b.w};
#pragma unroll
            for (int i = 0; i < 4; i++)
#pragma unroll
                for (int j = 0; j < 4; j++)
                    s[i][j] += av[i] * bvv[j];
        }
#pragma unroll
        for (int i = 0; i < 4; i++)
#pragma unroll
            for (int j = 0; j < 4; j++)
                Ps[(ty * 4 + i) * PS_LD + tx * 4 + j] = s[i][j] * scale;
        __syncthreads();

        {
            const int r = tid >> 2;
            const int part = tid & 3;
            float* prow = &Ps[r * PS_LD + part * 16];
            float mx = -1e30f;
#pragma unroll
            for (int c = 0; c < 16; c++) mx = fmaxf(mx, prow[c]);
            mx = fmaxf(mx, __shfl_xor_sync(0xffffffffu, mx, 1));
            mx = fmaxf(mx, __shfl_xor_sync(0xffffffffu, mx, 2));
            const float mold = rowm[r];
            const float mnew = fmaxf(mold, mx);
            float ssum = 0.f;
#pragma unroll
            for (int c = 0; c < 16; c++) {
                float e = __expf(prow[c] - mnew);
                prow[c] = e;
                ssum += e;
            }
            ssum += __shfl_xor_sync(0xffffffffu, ssum, 1);
            ssum += __shfl_xor_sync(0xffffffffu, ssum, 2);
            if (part == 0) {
                const float corr = __expf(mold - mnew);
                rowc[r] = corr;
                rowl[r] = rowl[r] * corr + ssum;
                rowm[r] = mnew;
            }
        }
        __syncthreads();

        float ci[4];
#pragma unroll
        for (int i = 0; i < 4; i++) ci[i] = rowc[ty * 4 + i];
#pragma unroll
        for (int i = 0; i < 4; i++)
#pragma unroll
            for (int c = 0; c < 8; c++) o[i][c] *= ci[i];

#pragma unroll 4
        for (int j = 0; j < BKV; j++) {
            float p[4];
#pragma unroll
            for (int i = 0; i < 4; i++) p[i] = Ps[(ty * 4 + i) * PS_LD + j];
            float4 v0 = *(const float4*)&Vs[j * VS_LD + tx * 8];
            float4 v1 = *(const float4*)&Vs[j * VS_LD + tx * 8 + 4];
            float vv[8] = {v0.x, v0.y, v0.z, v0.w, v1.x, v1.y, v1.z, v1.w};
#pragma unroll
            for (int i = 0; i < 4; i++)
#pragma unroll
                for (int c = 0; c < 8; c++)
                    o[i][c] += p[i] * vv[c];
        }
        __syncthreads();
    }

    const int b = bh >> 4;
    const int h = bh & 15;
#pragma unroll
    for (int i = 0; i < 4; i++) {
        const float inv = 1.f / rowl[ty * 4 + i];
        const int srow = q0 + ty * 4 + i;
        float* dst = &ctx[((size_t)(b * SEQ + srow)) * D_MODEL + h * HEAD_DIM + tx * 8];
        float4 o0, o1;
        o0.x = o[i][0] * inv; o0.y = o[i][1] * inv;
        o0.z = o[i][2] * inv; o0.w = o[i][3] * inv;
        o1.x = o[i][4] * inv; o1.y = o[i][5] * inv;
        o1.z = o[i][6] * inv; o1.w = o[i][7] * inv;
        *(float4*)dst = o0;
        *(float4*)(dst + 4) = o1;
    }
}

// ============================================================
extern "C" void kernel_launch(void* const* d_in, const int* in_sizes, int n_in,
                              void* d_out, int out_size)
{
    const float* x  = (const float*)d_in[0];
    const float* wq = (const float*)d_in[1];
    const float* bq = (const float*)d_in[2];
    const float* wk = (const float*)d_in[3];
    const float* bk = (const float*)d_in[4];
    const float* wv = (const float*)d_in[5];
    const float* bv = (const float*)d_in[6];
    const float* wo = (const float*)d_in[7];
    const float* bo = (const float*)d_in[8];
    float* out = (float*)d_out;

    float *q, *k, *v, *ctx;
    __nv_bfloat16 *xh, *xl, *wh, *wl, *ch, *cl;
    cudaGetSymbolAddress((void**)&q, g_q);
    cudaGetSymbolAddress((void**)&k, g_k);
    cudaGetSymbolAddress((void**)&v, g_v);
    cudaGetSymbolAddress((void**)&ctx, g_ctx);
    cudaGetSymbolAddress((void**)&xh, g_xh);
    cudaGetSymbolAddress((void**)&xl, g_xl);
    cudaGetSymbolAddress((void**)&wh, g_wh);
    cudaGetSymbolAddress((void**)&wl, g_wl);
    cudaGetSymbolAddress((void**)&ch, g_ch);
    cudaGetSymbolAddress((void**)&cl, g_cl);

    const size_t WN = (size_t)D_MODEL * D_MODEL;
    const int xn4 = (int)((size_t)MROWS * D_MODEL / 4);
    const int wn4 = (int)(WN / 4);

    split_kernel<<<(xn4 + 255) / 256, 256>>>(x, xh, xl, xn4);
    split_kernel<<<(wn4 + 255) / 256, 256>>>(wq, wh + 0 * WN, wl + 0 * WN, wn4);
    split_kernel<<<(wn4 + 255) / 256, 256>>>(wk, wh + 1 * WN, wl + 1 * WN, wn4);
    split_kernel<<<(wn4 + 255) / 256, 256>>>(wv, wh + 2 * WN, wl + 2 * WN, wn4);
    split_kernel<<<(wn4 + 255) / 256, 256>>>(wo, wh + 3 * WN, wl + 3 * WN, wn4);

    const int gsmem = 2 * BUFB;   // 81920
    cudaFuncSetAttribute(gemm_tc, cudaFuncAttributeMaxDynamicSharedMemorySize, gsmem);
    const dim3 ggrid(D_MODEL / 128, MROWS / 128);

    gemm_tc<<<ggrid, 256, gsmem>>>(xh, xl, wh + 0 * WN, wl + 0 * WN, bq, q, 1);
    gemm_tc<<<ggrid, 256, gsmem>>>(xh, xl, wh + 1 * WN, wl + 1 * WN, bk, k, 1);
    gemm_tc<<<ggrid, 256, gsmem>>>(xh, xl, wh + 2 * WN, wl + 2 * WN, bv, v, 1);

    const size_t asmem = (size_t)SMEM_FLOATS * sizeof(float);
    cudaFuncSetAttribute(attn_kernel, cudaFuncAttributeMaxDynamicSharedMemorySize, (int)asmem);
    attn_kernel<<<dim3(SEQ / BQ, BATCH * NUM_HEADS), 256, asmem>>>(q, k, v, ctx);

    split_kernel<<<(xn4 + 255) / 256, 256>>>(ctx, ch, cl, xn4);
    gemm_tc<<<ggrid, 256, gsmem>>>(ch, cl, wh + 3 * WN, wl + 3 * WN, bo, out, 0);
}

// round 4
// speedup vs baseline: 3.0469x; 2.1689x over previous
#include <cuda_runtime.h>
#include <cuda_bf16.h>
#include <cstdint>
#include <math.h>

#define D_MODEL 2048
#define NUM_HEADS 16
#define HEAD_DIM 128
#define BATCH 2
#define SEQ 2048
#define MROWS (BATCH*SEQ)
#define GK 2048
#define QSCALE 0.0883883476483184f   // 1/sqrt(128)

// ---------------- scratch (static; no allocations allowed) ----------------
#define QKV_ELEMS ((size_t)BATCH*NUM_HEADS*SEQ*HEAD_DIM)
__device__ __align__(256) __nv_bfloat16 g_qh[QKV_ELEMS];
__device__ __align__(256) __nv_bfloat16 g_ql[QKV_ELEMS];
__device__ __align__(256) __nv_bfloat16 g_kh[QKV_ELEMS];
__device__ __align__(256) __nv_bfloat16 g_kl[QKV_ELEMS];
__device__ __align__(256) __nv_bfloat16 g_vh[QKV_ELEMS];
__device__ __align__(256) __nv_bfloat16 g_vl[QKV_ELEMS];
__device__ __align__(256) __nv_bfloat16 g_xh[(size_t)MROWS*D_MODEL];
__device__ __align__(256) __nv_bfloat16 g_xl[(size_t)MROWS*D_MODEL];
__device__ __align__(256) __nv_bfloat16 g_wh[4][(size_t)D_MODEL*D_MODEL];
__device__ __align__(256) __nv_bfloat16 g_wl[4][(size_t)D_MODEL*D_MODEL];
__device__ __align__(256) __nv_bfloat16 g_ch[(size_t)MROWS*D_MODEL];
__device__ __align__(256) __nv_bfloat16 g_cl[(size_t)MROWS*D_MODEL];

// ---------------- helpers ----------------
__device__ __forceinline__ uint32_t smem_to_u32(const void* p) {
    uint32_t a;
    asm("{ .reg .u64 t; cvta.to.shared.u64 t, %1; cvt.u32.u64 %0, t; }" : "=r"(a) : "l"(p));
    return a;
}
__device__ __forceinline__ void ldsm4(uint32_t* r, uint32_t addr) {
    asm volatile("ldmatrix.sync.aligned.m8n8.x4.shared.b16 {%0,%1,%2,%3}, [%4];"
                 : "=r"(r[0]), "=r"(r[1]), "=r"(r[2]), "=r"(r[3]) : "r"(addr));
}
__device__ __forceinline__ void ldsm4t(uint32_t* r, uint32_t addr) {
    asm volatile("ldmatrix.sync.aligned.m8n8.x4.trans.shared.b16 {%0,%1,%2,%3}, [%4];"
                 : "=r"(r[0]), "=r"(r[1]), "=r"(r[2]), "=r"(r[3]) : "r"(addr));
}
__device__ __forceinline__ void mma_bf16(float* c, const uint32_t* a, const uint32_t* b) {
    asm volatile(
        "mma.sync.aligned.m16n8k16.row.col.f32.bf16.bf16.f32 "
        "{%0,%1,%2,%3}, {%4,%5,%6,%7}, {%8,%9}, {%0,%1,%2,%3};"
        : "+f"(c[0]), "+f"(c[1]), "+f"(c[2]), "+f"(c[3])
        : "r"(a[0]), "r"(a[1]), "r"(a[2]), "r"(a[3]), "r"(b[0]), "r"(b[1]));
}
__device__ __forceinline__ void cp16(uint32_t saddr, const void* gaddr) {
    asm volatile("cp.async.cg.shared.global [%0], [%1], 16;" :: "r"(saddr), "l"(gaddr));
}
#define CP_COMMIT() asm volatile("cp.async.commit_group;")
#define CP_WAIT(n)  asm volatile("cp.async.wait_group %0;" :: "n"(n))

// pack two fp32 -> bf16x2 (x0 in low half, x1 in high half)
__device__ __forceinline__ uint32_t pk2(float x0, float x1) {
    uint32_t r;
    asm("cvt.rn.bf16x2.f32 %0, %1, %2;" : "=r"(r) : "f"(x1), "f"(x0));
    return r;
}
__device__ __forceinline__ float bf16res(float x) {
    return x - __bfloat162float(__float2bfloat16(x));
}

// ---------------- split fp32 -> bf16 hi/lo ----------------
__global__ __launch_bounds__(256)
void split_kernel(const float* __restrict__ in, __nv_bfloat16* __restrict__ hi,
                  __nv_bfloat16* __restrict__ lo, int n4)
{
    int i = blockIdx.x * blockDim.x + threadIdx.x;
    if (i >= n4) return;
    float4 v = ((const float4*)in)[i];
    uint32_t h0 = pk2(v.x, v.y), h1 = pk2(v.z, v.w);
    uint32_t l0 = pk2(bf16res(v.x), bf16res(v.y));
    uint32_t l1 = pk2(bf16res(v.z), bf16res(v.w));
    ((uint32_t*)hi)[2 * i] = h0;
    ((uint32_t*)hi)[2 * i + 1] = h1;
    ((uint32_t*)lo)[2 * i] = l0;
    ((uint32_t*)lo)[2 * i + 1] = l1;
}

// ---------------- mma.sync split-bf16 GEMM: C = A @ W^T + bias ----------------
#define BKC 32
#define ROWB 80
#define TILE_BYTES (128*ROWB)
#define BUFB (4*TILE_BYTES)
#define NCH (GK/BKC)

__device__ __forceinline__ void load_chunk(uint32_t sbase,
                                           const __nv_bfloat16* g0, const __nv_bfloat16* g1,
                                           const __nv_bfloat16* g2, const __nv_bfloat16* g3,
                                           int k0, int tid)
{
    const __nv_bfloat16* gp[4] = {g0, g1, g2, g3};
#pragma unroll
    for (int t = 0; t < 8; t++) {
        const int id = tid + t * 256;
        const int tile = id >> 9;
        const int idx = id & 511;
        const int row = idx >> 2;
        const int c = idx & 3;
        uint32_t sa = sbase + tile * TILE_BYTES + row * ROWB + c * 16;
        const __nv_bfloat16* ga = gp[tile] + (size_t)row * GK + k0 + c * 8;
        cp16(sa, ga);
    }
    CP_COMMIT();
}

// mode 0: fp32 row-major [M, D_MODEL] to outf
// mode 1: bf16 hi/lo, scattered to [B,H,S,Dh], scaled by scl
__global__ __launch_bounds__(256, 1)
void gemm_tc(const __nv_bfloat16* __restrict__ Ah, const __nv_bfloat16* __restrict__ Al,
             const __nv_bfloat16* __restrict__ Wh, const __nv_bfloat16* __restrict__ Wl,
             const float* __restrict__ bias, float* __restrict__ outf,
             __nv_bfloat16* __restrict__ outh, __nv_bfloat16* __restrict__ outl,
             int mode, float scl)
{
    extern __shared__ char smem[];
    const uint32_t sb = smem_to_u32(smem);
    const int tid = threadIdx.x;
    const int lane = tid & 31;
    const int wid = tid >> 5;
    const int wm = wid >> 2;
    const int wn = wid & 3;
    const int n0 = blockIdx.x * 128;
    const int m0 = blockIdx.y * 128;

    const __nv_bfloat16* a_h = Ah + (size_t)m0 * GK;
    const __nv_bfloat16* a_l = Al + (size_t)m0 * GK;
    const __nv_bfloat16* b_h = Wh + (size_t)n0 * GK;
    const __nv_bfloat16* b_l = Wl + (size_t)n0 * GK;

    float acc[4][4][4];
#pragma unroll
    for (int mi = 0; mi < 4; mi++)
#pragma unroll
        for (int ni = 0; ni < 4; ni++)
#pragma unroll
            for (int e = 0; e < 4; e++) acc[mi][ni][e] = 0.f;

    load_chunk(sb, a_h, a_l, b_h, b_l, 0, tid);

    for (int ch = 0; ch < NCH; ch++) {
        if (ch + 1 < NCH) {
            load_chunk(sb + ((ch + 1) & 1) * BUFB, a_h, a_l, b_h, b_l, (ch + 1) * BKC, tid);
            CP_WAIT(1);
        } else {
            CP_WAIT(0);
        }
        __syncthreads();

        const uint32_t base = sb + (ch & 1) * BUFB;
        const uint32_t aBaseH = base;
        const uint32_t aBaseL = base + TILE_BYTES;
        const uint32_t bBaseH = base + 2 * TILE_BYTES;
        const uint32_t bBaseL = base + 3 * TILE_BYTES;

#pragma unroll
        for (int kk = 0; kk < 2; kk++) {
            uint32_t ah[4][4], al[4][4], bh[4][2], bl[4][2];
            const int arow = wm * 64 + (lane & 15);
            const uint32_t aoff = ((lane >> 4) * 16) + kk * 32;
#pragma unroll
            for (int mi = 0; mi < 4; mi++) {
                ldsm4(ah[mi], aBaseH + (arow + mi * 16) * ROWB + aoff);
                ldsm4(al[mi], aBaseL + (arow + mi * 16) * ROWB + aoff);
            }
            const int brow = wn * 32 + (lane & 7);
            const uint32_t boff = (((lane >> 3) & 1) * 16) + kk * 32;
#pragma unroll
            for (int ni = 0; ni < 4; ni++) {
                asm volatile("ldmatrix.sync.aligned.m8n8.x2.shared.b16 {%0,%1}, [%2];"
                             : "=r"(bh[ni][0]), "=r"(bh[ni][1])
                             : "r"(bBaseH + (brow + ni * 8) * ROWB + boff));
                asm volatile("ldmatrix.sync.aligned.m8n8.x2.shared.b16 {%0,%1}, [%2];"
                             : "=r"(bl[ni][0]), "=r"(bl[ni][1])
                             : "r"(bBaseL + (brow + ni * 8) * ROWB + boff));
            }
#pragma unroll
            for (int mi = 0; mi < 4; mi++)
#pragma unroll
                for (int ni = 0; ni < 4; ni++) {
                    mma_bf16(acc[mi][ni], ah[mi], bh[ni]);
                    mma_bf16(acc[mi][ni], ah[mi], bl[ni]);
                    mma_bf16(acc[mi][ni], al[mi], bh[ni]);
                }
        }
        __syncthreads();
    }

    const int r = lane >> 2;
    const int cp = (lane & 3) * 2;
    const int mbase = m0 + wm * 64;
    const int nbase = n0 + wn * 32;
#pragma unroll
    for (int mi = 0; mi < 4; mi++) {
#pragma unroll
        for (int ni = 0; ni < 4; ni++) {
            const int n_g = nbase + ni * 8 + cp;
            const float b0v = bias[n_g], b1v = bias[n_g + 1];
            const int m0g = mbase + mi * 16 + r;
            const int m1g = m0g + 8;
            float v0x = (acc[mi][ni][0] + b0v) * scl;
            float v0y = (acc[mi][ni][1] + b1v) * scl;
            float v1x = (acc[mi][ni][2] + b0v) * scl;
            float v1y = (acc[mi][ni][3] + b1v) * scl;
            if (mode == 0) {
                float2 v0 = {v0x, v0y}, v1 = {v1x, v1y};
                *(float2*)&outf[(size_t)m0g * D_MODEL + n_g] = v0;
                *(float2*)&outf[(size_t)m1g * D_MODEL + n_g] = v1;
            } else {
                const int h = n0 >> 7;
                const int d = n_g & 127;
                const int b0i = m0g >> 11, s0 = m0g & 2047;
                const int b1i = m1g >> 11, s1 = m1g & 2047;
                const size_t i0 = (((size_t)(b0i * NUM_HEADS + h) * SEQ + s0) * HEAD_DIM) + d;
                const size_t i1 = (((size_t)(b1i * NUM_HEADS + h) * SEQ + s1) * HEAD_DIM) + d;
                *(uint32_t*)&outh[i0] = pk2(v0x, v0y);
                *(uint32_t*)&outl[i0] = pk2(bf16res(v0x), bf16res(v0y));
                *(uint32_t*)&outh[i1] = pk2(v1x, v1y);
                *(uint32_t*)&outl[i1] = pk2(bf16res(v1x), bf16res(v1y));
            }
        }
    }
}

// ============================================================
// Flash attention, split-bf16 mma.sync
// CTA: 128 queries, 8 warps (16 rows each). KV tiles of 64, double-buffered.
// ============================================================
#define ABQ 128
#define ABKV 64
#define AQ_BYTES 32768          // 128 rows x 256B
#define AKV_TILE 16384          // 64 rows x 256B
#define AKV_BUF  (4*AKV_TILE)   // Kh,Kl,Vh,Vl
#define AKV_BASE (2*AQ_BYTES)
#define ASMEM (AKV_BASE + 2*AKV_BUF)   // 196608

__device__ __forceinline__ void attn_load_kv(uint32_t sbuf,
    const __nv_bfloat16* kh_, const __nv_bfloat16* kl_,
    const __nv_bfloat16* vh_, const __nv_bfloat16* vl_,
    int kv0, int tid)
{
    const __nv_bfloat16* gp[4] = {kh_, kl_, vh_, vl_};
#pragma unroll
    for (int i = 0; i < 16; i++) {
        int id = i * 256 + tid;
        int tile = id >> 10;
        int idx = id & 1023;
        int row = idx >> 4;
        int cc = idx & 15;
        uint32_t dst = sbuf + tile * AKV_TILE + row * 256 + (((cc ^ (row & 7))) << 4);
        cp16(dst, gp[tile] + (size_t)(kv0 + row) * HEAD_DIM + cc * 8);
    }
    CP_COMMIT();
}

__global__ __launch_bounds__(256, 1)
void attn_tc(const __nv_bfloat16* __restrict__ qh, const __nv_bfloat16* __restrict__ ql,
             const __nv_bfloat16* __restrict__ kh, const __nv_bfloat16* __restrict__ kl,
             const __nv_bfloat16* __restrict__ vh, const __nv_bfloat16* __restrict__ vl,
             __nv_bfloat16* __restrict__ ch, __nv_bfloat16* __restrict__ cl)
{
    extern __shared__ char smem[];
    const uint32_t sb = smem_to_u32(smem);
    const int tid = threadIdx.x;
    const int lane = tid & 31;
    const int w = tid >> 5;
    const int bh = blockIdx.y;
    const int q0 = blockIdx.x * ABQ;
    const size_t base = (size_t)bh * SEQ * HEAD_DIM;

    // Q tiles (hi+lo)
    {
        const __nv_bfloat16* gq[2] = {qh + base, ql + base};
#pragma unroll
        for (int i = 0; i < 16; i++) {
            int id = i * 256 + tid;
            int tile = id >> 11;
            int idx = id & 2047;
            int row = idx >> 4;
            int cc = idx & 15;
            uint32_t dst = sb + tile * AQ_BYTES + row * 256 + (((cc ^ (row & 7))) << 4);
            cp16(dst, gq[tile] + (size_t)(q0 + row) * HEAD_DIM + cc * 8);
        }
        CP_COMMIT();
    }
    attn_load_kv(sb + AKV_BASE, kh + base, kl + base, vh + base, vl + base, 0, tid);

    float o[16][4];
#pragma unroll
    for (int ni = 0; ni < 16; ni++)
#pragma unroll
        for (int e = 0; e < 4; e++) o[ni][e] = 0.f;
    float m0 = -1e30f, m1 = -1e30f, l0 = 0.f, l1 = 0.f;

    const int NKV = SEQ / ABKV;
    for (int it = 0; it < NKV; it++) {
        if (it + 1 < NKV) {
            attn_load_kv(sb + AKV_BASE + ((it + 1) & 1) * AKV_BUF,
                         kh + base, kl + base, vh + base, vl + base, (it + 1) * ABKV, tid);
            CP_WAIT(1);
        } else {
            CP_WAIT(0);
        }
        __syncthreads();

        const uint32_t khb = sb + AKV_BASE + (it & 1) * AKV_BUF;
        const uint32_t klb = khb + AKV_TILE;
        const uint32_t vhb = khb + 2 * AKV_TILE;
        const uint32_t vlb = khb + 3 * AKV_TILE;

        // ---- S = Q K^T (3-term split), S tile per warp: 16 x 64
        float s[8][4];
#pragma unroll
        for (int ni = 0; ni < 8; ni++) {
            s[ni][0] = 0.f; s[ni][1] = 0.f; s[ni][2] = 0.f; s[ni][3] = 0.f;
        }
#pragma unroll
        for (int ks = 0; ks < 8; ks++) {
            uint32_t aQh[4], aQl[4];
            const int qrow = 16 * w + (lane & 15);
            const int qcc = ks * 2 + (lane >> 4);
            const uint32_t qoff = qrow * 256 + (((qcc ^ (qrow & 7))) << 4);
            ldsm4(aQh, sb + qoff);
            ldsm4(aQl, sb + AQ_BYTES + qoff);
#pragma unroll
            for (int np = 0; np < 4; np++) {
                uint32_t bKh[4], bKl[4];
                const int krow = np * 16 + ((lane >> 4) << 3) + (lane & 7);
                const int kcc = ks * 2 + ((lane >> 3) & 1);
                const uint32_t koff = krow * 256 + (((kcc ^ (krow & 7))) << 4);
                ldsm4(bKh, khb + koff);
                ldsm4(bKl, klb + koff);
                mma_bf16(s[2 * np],     aQh, bKh);
                mma_bf16(s[2 * np],     aQh, bKl);
                mma_bf16(s[2 * np],     aQl, bKh);
                mma_bf16(s[2 * np + 1], aQh, bKh + 2);
                mma_bf16(s[2 * np + 1], aQh, bKl + 2);
                mma_bf16(s[2 * np + 1], aQl, bKh + 2);
            }
        }

        // ---- online softmax (rows r=lane>>2 and r+8)
        float mx0 = -1e30f, mx1 = -1e30f;
#pragma unroll
        for (int ni = 0; ni < 8; ni++) {
            mx0 = fmaxf(mx0, fmaxf(s[ni][0], s[ni][1]));
            mx1 = fmaxf(mx1, fmaxf(s[ni][2], s[ni][3]));
        }
        mx0 = fmaxf(mx0, __shfl_xor_sync(0xffffffffu, mx0, 1));
        mx0 = fmaxf(mx0, __shfl_xor_sync(0xffffffffu, mx0, 2));
        mx1 = fmaxf(mx1, __shfl_xor_sync(0xffffffffu, mx1, 1));
        mx1 = fmaxf(mx1, __shfl_xor_sync(0xffffffffu, mx1, 2));
        const float mn0 = fmaxf(m0, mx0), mn1 = fmaxf(m1, mx1);
        const float c0 = __expf(m0 - mn0), c1 = __expf(m1 - mn1);
        m0 = mn0; m1 = mn1;
        float r0s = 0.f, r1s = 0.f;
#pragma unroll
        for (int ni = 0; ni < 8; ni++) {
            s[ni][0] = __expf(s[ni][0] - mn0);
            s[ni][1] = __expf(s[ni][1] - mn0);
            s[ni][2] = __expf(s[ni][2] - mn1);
            s[ni][3] = __expf(s[ni][3] - mn1);
            r0s += s[ni][0] + s[ni][1];
            r1s += s[ni][2] + s[ni][3];
        }
        l0 = l0 * c0 + r0s;
        l1 = l1 * c1 + r1s;
#pragma unroll
        for (int ni = 0; ni < 16; ni++) {
            o[ni][0] *= c0; o[ni][1] *= c0; o[ni][2] *= c1; o[ni][3] *= c1;
        }

        // ---- O += P V (3-term split); P frags from S accumulators
#pragma unroll
        for (int t = 0; t < 4; t++) {
            uint32_t aPh[4], aPl[4];
            aPh[0] = pk2(s[2 * t][0], s[2 * t][1]);
            aPh[1] = pk2(s[2 * t][2], s[2 * t][3]);
            aPh[2] = pk2(s[2 * t + 1][0], s[2 * t + 1][1]);
            aPh[3] = pk2(s[2 * t + 1][2], s[2 * t + 1][3]);
            aPl[0] = pk2(bf16res(s[2 * t][0]), bf16res(s[2 * t][1]));
            aPl[1] = pk2(bf16res(s[2 * t][2]), bf16res(s[2 * t][3]));
            aPl[2] = pk2(bf16res(s[2 * t + 1][0]), bf16res(s[2 * t + 1][1]));
            aPl[3] = pk2(bf16res(s[2 * t + 1][2]), bf16res(s[2 * t + 1][3]));
#pragma unroll
            for (int np = 0; np < 8; np++) {
                uint32_t bVh[4], bVl[4];
                const int vrow = t * 16 + (lane & 7) + ((lane >> 3) & 1) * 8;
                const int vcc = np * 2 + (lane >> 4);
                const uint32_t voff = vrow * 256 + (((vcc ^ (vrow & 7))) << 4);
                ldsm4t(bVh, vhb + voff);
                ldsm4t(bVl, vlb + voff);
                mma_bf16(o[2 * np],     aPh, bVh);
                mma_bf16(o[2 * np],     aPh, bVl);
                mma_bf16(o[2 * np],     aPl, bVh);
                mma_bf16(o[2 * np + 1], aPh, bVh + 2);
                mma_bf16(o[2 * np + 1], aPh, bVl + 2);
                mma_bf16(o[2 * np + 1], aPl, bVh + 2);
            }
        }
        __syncthreads();
    }

    // ---- finalize: divide by l, write ctx as bf16 hi/lo [B,S,D]
    float lt0 = l0, lt1 = l1;
    lt0 += __shfl_xor_sync(0xffffffffu, lt0, 1);
    lt0 += __shfl_xor_sync(0xffffffffu, lt0, 2);
    lt1 += __shfl_xor_sync(0xffffffffu, lt1, 1);
    lt1 += __shfl_xor_sync(0xffffffffu, lt1, 2);
    const float inv0 = 1.f / lt0, inv1 = 1.f / lt1;

    const int b = bh >> 4, h = bh & 15;
    const int r = lane >> 2, cpp = (lane & 3) * 2;
    const int qr0 = q0 + 16 * w + r, qr1 = qr0 + 8;
#pragma unroll
    for (int ni = 0; ni < 16; ni++) {
        const int d = ni * 8 + cpp;
        const size_t i0 = ((size_t)(b * SEQ + qr0)) * D_MODEL + h * HEAD_DIM + d;
        const size_t i1 = ((size_t)(b * SEQ + qr1)) * D_MODEL + h * HEAD_DIM + d;
        float f0 = o[ni][0] * inv0, f1 = o[ni][1] * inv0;
        float f2 = o[ni][2] * inv1, f3 = o[ni][3] * inv1;
        *(uint32_t*)&ch[i0] = pk2(f0, f1);
        *(uint32_t*)&cl[i0] = pk2(bf16res(f0), bf16res(f1));
        *(uint32_t*)&ch[i1] = pk2(f2, f3);
        *(uint32_t*)&cl[i1] = pk2(bf16res(f2), bf16res(f3));
    }
}

// ============================================================
extern "C" void kernel_launch(void* const* d_in, const int* in_sizes, int n_in,
                              void* d_out, int out_size)
{
    const float* x  = (const float*)d_in[0];
    const float* wq = (const float*)d_in[1];
    const float* bq = (const float*)d_in[2];
    const float* wk = (const float*)d_in[3];
    const float* bk = (const float*)d_in[4];
    const float* wv = (const float*)d_in[5];
    const float* bv = (const float*)d_in[6];
    const float* wo = (const float*)d_in[7];
    const float* bo = (const float*)d_in[8];
    float* out = (float*)d_out;

    __nv_bfloat16 *xh, *xl, *wh, *wl, *ch, *cl, *qh, *ql, *kh, *kl, *vh, *vl;
    cudaGetSymbolAddress((void**)&xh, g_xh);
    cudaGetSymbolAddress((void**)&xl, g_xl);
    cudaGetSymbolAddress((void**)&wh, g_wh);
    cudaGetSymbolAddress((void**)&wl, g_wl);
    cudaGetSymbolAddress((void**)&ch, g_ch);
    cudaGetSymbolAddress((void**)&cl, g_cl);
    cudaGetSymbolAddress((void**)&qh, g_qh);
    cudaGetSymbolAddress((void**)&ql, g_ql);
    cudaGetSymbolAddress((void**)&kh, g_kh);
    cudaGetSymbolAddress((void**)&kl, g_kl);
    cudaGetSymbolAddress((void**)&vh, g_vh);
    cudaGetSymbolAddress((void**)&vl, g_vl);

    const size_t WN = (size_t)D_MODEL * D_MODEL;
    const int xn4 = (int)((size_t)MROWS * D_MODEL / 4);
    const int wn4 = (int)(WN / 4);

    split_kernel<<<(xn4 + 255) / 256, 256>>>(x, xh, xl, xn4);
    split_kernel<<<(wn4 + 255) / 256, 256>>>(wq, wh + 0 * WN, wl + 0 * WN, wn4);
    split_kernel<<<(wn4 + 255) / 256, 256>>>(wk, wh + 1 * WN, wl + 1 * WN, wn4);
    split_kernel<<<(wn4 + 255) / 256, 256>>>(wv, wh + 2 * WN, wl + 2 * WN, wn4);
    split_kernel<<<(wn4 + 255) / 256, 256>>>(wo, wh + 3 * WN, wl + 3 * WN, wn4);

    const int gsmem = 2 * BUFB;
    cudaFuncSetAttribute(gemm_tc, cudaFuncAttributeMaxDynamicSharedMemorySize, gsmem);
    const dim3 ggrid(D_MODEL / 128, MROWS / 128);

    gemm_tc<<<ggrid, 256, gsmem>>>(xh, xl, wh + 0 * WN, wl + 0 * WN, bq,
                                   nullptr, qh, ql, 1, QSCALE);
    gemm_tc<<<ggrid, 256, gsmem>>>(xh, xl, wh + 1 * WN, wl + 1 * WN, bk,
                                   nullptr, kh, kl, 1, 1.0f);
    gemm_tc<<<ggrid, 256, gsmem>>>(xh, xl, wh + 2 * WN, wl + 2 * WN, bv,
                                   nullptr, vh, vl, 1, 1.0f);

    cudaFuncSetAttribute(attn_tc, cudaFuncAttributeMaxDynamicSharedMemorySize, ASMEM);
    attn_tc<<<dim3(SEQ / ABQ, BATCH * NUM_HEADS), 256, ASMEM>>>(qh, ql, kh, kl, vh, vl, ch, cl);

    gemm_tc<<<ggrid, 256, gsmem>>>(ch, cl, wh + 3 * WN, wl + 3 * WN, bo,
                                   out, nullptr, nullptr, 0, 1.0f);
}

// round 5
// speedup vs baseline: 3.3753x; 1.1078x over previous
#include <cuda_runtime.h>
#include <cuda_bf16.h>
#include <cstdint>
#include <math.h>

#define D_MODEL 2048
#define NUM_HEADS 16
#define HEAD_DIM 128
#define BATCH 2
#define SEQ 2048
#define MROWS (BATCH*SEQ)
#define GK 2048
#define QSCALE 0.0883883476483184f   // 1/sqrt(128)

// ---------------- scratch (static; no allocations allowed) ----------------
#define QKV_ELEMS ((size_t)BATCH*NUM_HEADS*SEQ*HEAD_DIM)
__device__ __align__(256) __nv_bfloat16 g_qh[QKV_ELEMS];
__device__ __align__(256) __nv_bfloat16 g_ql[QKV_ELEMS];
__device__ __align__(256) __nv_bfloat16 g_kh[QKV_ELEMS];
__device__ __align__(256) __nv_bfloat16 g_kl[QKV_ELEMS];
__device__ __align__(256) __nv_bfloat16 g_vh[QKV_ELEMS];
__device__ __align__(256) __nv_bfloat16 g_vl[QKV_ELEMS];
__device__ __align__(256) __nv_bfloat16 g_xh[(size_t)MROWS*D_MODEL];
__device__ __align__(256) __nv_bfloat16 g_xl[(size_t)MROWS*D_MODEL];
__device__ __align__(256) __nv_bfloat16 g_wh[4][(size_t)D_MODEL*D_MODEL];
__device__ __align__(256) __nv_bfloat16 g_wl[4][(size_t)D_MODEL*D_MODEL];
__device__ __align__(256) __nv_bfloat16 g_ch[(size_t)MROWS*D_MODEL];
__device__ __align__(256) __nv_bfloat16 g_cl[(size_t)MROWS*D_MODEL];

// ---------------- helpers ----------------
__device__ __forceinline__ uint32_t smem_to_u32(const void* p) {
    uint32_t a;
    asm("{ .reg .u64 t; cvta.to.shared.u64 t, %1; cvt.u32.u64 %0, t; }" : "=r"(a) : "l"(p));
    return a;
}
__device__ __forceinline__ void ldsm4(uint32_t* r, uint32_t addr) {
    asm volatile("ldmatrix.sync.aligned.m8n8.x4.shared.b16 {%0,%1,%2,%3}, [%4];"
                 : "=r"(r[0]), "=r"(r[1]), "=r"(r[2]), "=r"(r[3]) : "r"(addr));
}
__device__ __forceinline__ void ldsm4t(uint32_t* r, uint32_t addr) {
    asm volatile("ldmatrix.sync.aligned.m8n8.x4.trans.shared.b16 {%0,%1,%2,%3}, [%4];"
                 : "=r"(r[0]), "=r"(r[1]), "=r"(r[2]), "=r"(r[3]) : "r"(addr));
}
__device__ __forceinline__ void mma_bf16(float* c, const uint32_t* a, const uint32_t* b) {
    asm volatile(
        "mma.sync.aligned.m16n8k16.row.col.f32.bf16.bf16.f32 "
        "{%0,%1,%2,%3}, {%4,%5,%6,%7}, {%8,%9}, {%0,%1,%2,%3};"
        : "+f"(c[0]), "+f"(c[1]), "+f"(c[2]), "+f"(c[3])
        : "r"(a[0]), "r"(a[1]), "r"(a[2]), "r"(a[3]), "r"(b[0]), "r"(b[1]));
}
__device__ __forceinline__ void cp16(uint32_t saddr, const void* gaddr) {
    asm volatile("cp.async.cg.shared.global [%0], [%1], 16;" :: "r"(saddr), "l"(gaddr));
}
#define CP_COMMIT() asm volatile("cp.async.commit_group;")
#define CP_WAIT(n)  asm volatile("cp.async.wait_group %0;" :: "n"(n))

__device__ __forceinline__ uint32_t pk2(float x0, float x1) {
    uint32_t r;
    asm("cvt.rn.bf16x2.f32 %0, %1, %2;" : "=r"(r) : "f"(x1), "f"(x0));
    return r;
}
__device__ __forceinline__ float bf16res(float x) {
    return x - __bfloat162float(__float2bfloat16(x));
}

// ---------------- split fp32 -> bf16 hi/lo ----------------
__global__ __launch_bounds__(256)
void split_kernel(const float* __restrict__ in, __nv_bfloat16* __restrict__ hi,
                  __nv_bfloat16* __restrict__ lo, int n4)
{
    int i = blockIdx.x * blockDim.x + threadIdx.x;
    if (i >= n4) return;
    float4 v = ((const float4*)in)[i];
    ((uint32_t*)hi)[2 * i]     = pk2(v.x, v.y);
    ((uint32_t*)hi)[2 * i + 1] = pk2(v.z, v.w);
    ((uint32_t*)lo)[2 * i]     = pk2(bf16res(v.x), bf16res(v.y));
    ((uint32_t*)lo)[2 * i + 1] = pk2(bf16res(v.z), bf16res(v.w));
}

// fused 4-weight split: blockIdx.y selects the weight matrix
__global__ __launch_bounds__(256)
void split_w4(const float* __restrict__ w0, const float* __restrict__ w1,
              const float* __restrict__ w2, const float* __restrict__ w3,
              __nv_bfloat16* __restrict__ hi, __nv_bfloat16* __restrict__ lo, int n4)
{
    const float* ws[4] = {w0, w1, w2, w3};
    const float* in = ws[blockIdx.y];
    __nv_bfloat16* h = hi + (size_t)blockIdx.y * D_MODEL * D_MODEL;
    __nv_bfloat16* l = lo + (size_t)blockIdx.y * D_MODEL * D_MODEL;
    int i = blockIdx.x * blockDim.x + threadIdx.x;
    if (i >= n4) return;
    float4 v = ((const float4*)in)[i];
    ((uint32_t*)h)[2 * i]     = pk2(v.x, v.y);
    ((uint32_t*)h)[2 * i + 1] = pk2(v.z, v.w);
    ((uint32_t*)l)[2 * i]     = pk2(bf16res(v.x), bf16res(v.y));
    ((uint32_t*)l)[2 * i + 1] = pk2(bf16res(v.z), bf16res(v.w));
}

// ---------------- mma.sync split-bf16 GEMM: C = A @ W^T + bias ----------------
// CTA tile 128x128, BK=64, 256 threads = 8 warps (2x4), warp tile 64x32.
// SMEM row stride 144B (128 data + 16 pad -> conflict-free ldmatrix, no swizzle).
#define BKC 64
#define ROWB 144
#define TILE_BYTES (128*ROWB)      // 18432
#define BUFB (4*TILE_BYTES)        // 73728
#define NCH (GK/BKC)               // 32

__device__ __forceinline__ void load_chunk(uint32_t sbase,
                                           const __nv_bfloat16* g0, const __nv_bfloat16* g1,
                                           const __nv_bfloat16* g2, const __nv_bfloat16* g3,
                                           int k0, int tid)
{
    const __nv_bfloat16* gp[4] = {g0, g1, g2, g3};
#pragma unroll
    for (int t = 0; t < 16; t++) {
        const int id = tid + t * 256;
        const int tile = id >> 10;          // 1024 cp16 per tile
        const int idx = id & 1023;
        const int row = idx >> 3;
        const int c = idx & 7;
        uint32_t sa = sbase + tile * TILE_BYTES + row * ROWB + c * 16;
        const __nv_bfloat16* ga = gp[tile] + (size_t)row * GK + k0 + c * 8;
        cp16(sa, ga);
    }
    CP_COMMIT();
}

// mode 0: fp32 row-major to outf;  mode 1: bf16 hi/lo scattered to [B,H,S,Dh], scaled
__global__ __launch_bounds__(256, 1)
void gemm_tc(const __nv_bfloat16* __restrict__ Ah, const __nv_bfloat16* __restrict__ Al,
             const __nv_bfloat16* __restrict__ Wh, const __nv_bfloat16* __restrict__ Wl,
             const float* __restrict__ bias, float* __restrict__ outf,
             __nv_bfloat16* __restrict__ outh, __nv_bfloat16* __restrict__ outl,
             int mode, float scl)
{
    extern __shared__ char smem[];
    const uint32_t sb = smem_to_u32(smem);
    const int tid = threadIdx.x;
    const int lane = tid & 31;
    const int wid = tid >> 5;
    const int wm = wid >> 2;
    const int wn = wid & 3;
    const int n0 = blockIdx.x * 128;
    const int m0 = blockIdx.y * 128;

    const __nv_bfloat16* a_h = Ah + (size_t)m0 * GK;
    const __nv_bfloat16* a_l = Al + (size_t)m0 * GK;
    const __nv_bfloat16* b_h = Wh + (size_t)n0 * GK;
    const __nv_bfloat16* b_l = Wl + (size_t)n0 * GK;

    float acc[4][4][4];
#pragma unroll
    for (int mi = 0; mi < 4; mi++)
#pragma unroll
        for (int ni = 0; ni < 4; ni++)
#pragma unroll
            for (int e = 0; e < 4; e++) acc[mi][ni][e] = 0.f;

    load_chunk(sb, a_h, a_l, b_h, b_l, 0, tid);

    // precomputed ldmatrix address components
    const int arow = wm * 64 + (lane & 15);
    const uint32_t aoff0 = (lane >> 4) * 16;
    const int brow = wn * 32 + ((lane >> 4) << 3) + (lane & 7);
    const uint32_t boff0 = ((lane >> 3) & 1) * 16;

    for (int ch = 0; ch < NCH; ch++) {
        if (ch + 1 < NCH) {
            load_chunk(sb + ((ch + 1) & 1) * BUFB, a_h, a_l, b_h, b_l, (ch + 1) * BKC, tid);
            CP_WAIT(1);
        } else {
            CP_WAIT(0);
        }
        __syncthreads();

        const uint32_t base = sb + (ch & 1) * BUFB;
        const uint32_t aBaseH = base;
        const uint32_t aBaseL = base + TILE_BYTES;
        const uint32_t bBaseH = base + 2 * TILE_BYTES;
        const uint32_t bBaseL = base + 3 * TILE_BYTES;

#pragma unroll
        for (int kk = 0; kk < 4; kk++) {
            uint32_t ah[4][4], al[4][4], bh[2][4], bl[2][4];
            const uint32_t aoff = aoff0 + kk * 32;
#pragma unroll
            for (int mi = 0; mi < 4; mi++) {
                ldsm4(ah[mi], aBaseH + (arow + mi * 16) * ROWB + aoff);
                ldsm4(al[mi], aBaseL + (arow + mi * 16) * ROWB + aoff);
            }
            const uint32_t boff = boff0 + kk * 32;
#pragma unroll
            for (int p = 0; p < 2; p++) {
                ldsm4(bh[p], bBaseH + (brow + p * 16) * ROWB + boff);
                ldsm4(bl[p], bBaseL + (brow + p * 16) * ROWB + boff);
            }
#pragma unroll
            for (int mi = 0; mi < 4; mi++)
#pragma unroll
                for (int p = 0; p < 2; p++) {
                    mma_bf16(acc[mi][2 * p],     ah[mi], bh[p]);
                    mma_bf16(acc[mi][2 * p],     ah[mi], bl[p]);
                    mma_bf16(acc[mi][2 * p],     al[mi], bh[p]);
                    mma_bf16(acc[mi][2 * p + 1], ah[mi], bh[p] + 2);
                    mma_bf16(acc[mi][2 * p + 1], ah[mi], bl[p] + 2);
                    mma_bf16(acc[mi][2 * p + 1], al[mi], bh[p] + 2);
                }
        }
        __syncthreads();
    }

    const int r = lane >> 2;
    const int cp = (lane & 3) * 2;
    const int mbase = m0 + wm * 64;
    const int nbase = n0 + wn * 32;
#pragma unroll
    for (int mi = 0; mi < 4; mi++) {
#pragma unroll
        for (int ni = 0; ni < 4; ni++) {
            const int n_g = nbase + ni * 8 + cp;
            const float b0v = bias[n_g], b1v = bias[n_g + 1];
            const int m0g = mbase + mi * 16 + r;
            const int m1g = m0g + 8;
            float v0x = (acc[mi][ni][0] + b0v) * scl;
            float v0y = (acc[mi][ni][1] + b1v) * scl;
            float v1x = (acc[mi][ni][2] + b0v) * scl;
            float v1y = (acc[mi][ni][3] + b1v) * scl;
            if (mode == 0) {
                float2 v0 = {v0x, v0y}, v1 = {v1x, v1y};
                *(float2*)&outf[(size_t)m0g * D_MODEL + n_g] = v0;
                *(float2*)&outf[(size_t)m1g * D_MODEL + n_g] = v1;
            } else {
                const int h = n0 >> 7;
                const int d = n_g & 127;
                const int b0i = m0g >> 11, s0 = m0g & 2047;
                const int b1i = m1g >> 11, s1 = m1g & 2047;
                const size_t i0 = (((size_t)(b0i * NUM_HEADS + h) * SEQ + s0) * HEAD_DIM) + d;
                const size_t i1 = (((size_t)(b1i * NUM_HEADS + h) * SEQ + s1) * HEAD_DIM) + d;
                *(uint32_t*)&outh[i0] = pk2(v0x, v0y);
                *(uint32_t*)&outl[i0] = pk2(bf16res(v0x), bf16res(v0y));
                *(uint32_t*)&outh[i1] = pk2(v1x, v1y);
                *(uint32_t*)&outl[i1] = pk2(bf16res(v1x), bf16res(v1y));
            }
        }
    }
}

// ============================================================
// Flash attention, split-bf16 mma.sync (unchanged from round 4)
// ============================================================
#define ABQ 128
#define ABKV 64
#define AQ_BYTES 32768
#define AKV_TILE 16384
#define AKV_BUF  (4*AKV_TILE)
#define AKV_BASE (2*AQ_BYTES)
#define ASMEM (AKV_BASE + 2*AKV_BUF)

__device__ __forceinline__ void attn_load_kv(uint32_t sbuf,
    const __nv_bfloat16* kh_, const __nv_bfloat16* kl_,
    const __nv_bfloat16* vh_, const __nv_bfloat16* vl_,
    int kv0, int tid)
{
    const __nv_bfloat16* gp[4] = {kh_, kl_, vh_, vl_};
#pragma unroll
    for (int i = 0; i < 16; i++) {
        int id = i * 256 + tid;
        int tile = id >> 10;
        int idx = id & 1023;
        int row = idx >> 4;
        int cc = idx & 15;
        uint32_t dst = sbuf + tile * AKV_TILE + row * 256 + (((cc ^ (row & 7))) << 4);
        cp16(dst, gp[tile] + (size_t)(kv0 + row) * HEAD_DIM + cc * 8);
    }
    CP_COMMIT();
}

__global__ __launch_bounds__(256, 1)
void attn_tc(const __nv_bfloat16* __restrict__ qh, const __nv_bfloat16* __restrict__ ql,
             const __nv_bfloat16* __restrict__ kh, const __nv_bfloat16* __restrict__ kl,
             const __nv_bfloat16* __restrict__ vh, const __nv_bfloat16* __restrict__ vl,
             __nv_bfloat16* __restrict__ ch, __nv_bfloat16* __restrict__ cl)
{
    extern __shared__ char smem[];
    const uint32_t sb = smem_to_u32(smem);
    const int tid = threadIdx.x;
    const int lane = tid & 31;
    const int w = tid >> 5;
    const int bh = blockIdx.y;
    const int q0 = blockIdx.x * ABQ;
    const size_t base = (size_t)bh * SEQ * HEAD_DIM;

    {
        const __nv_bfloat16* gq[2] = {qh + base, ql + base};
#pragma unroll
        for (int i = 0; i < 16; i++) {
            int id = i * 256 + tid;
            int tile = id >> 11;
            int idx = id & 2047;
            int row = idx >> 4;
            int cc = idx & 15;
            uint32_t dst = sb + tile * AQ_BYTES + row * 256 + (((cc ^ (row & 7))) << 4);
            cp16(dst, gq[tile] + (size_t)(q0 + row) * HEAD_DIM + cc * 8);
        }
        CP_COMMIT();
    }
    attn_load_kv(sb + AKV_BASE, kh + base, kl + base, vh + base, vl + base, 0, tid);

    float o[16][4];
#pragma unroll
    for (int ni = 0; ni < 16; ni++)
#pragma unroll
        for (int e = 0; e < 4; e++) o[ni][e] = 0.f;
    float m0 = -1e30f, m1 = -1e30f, l0 = 0.f, l1 = 0.f;

    const int NKV = SEQ / ABKV;
    for (int it = 0; it < NKV; it++) {
        if (it + 1 < NKV) {
            attn_load_kv(sb + AKV_BASE + ((it + 1) & 1) * AKV_BUF,
                         kh + base, kl + base, vh + base, vl + base, (it + 1) * ABKV, tid);
            CP_WAIT(1);
        } else {
            CP_WAIT(0);
        }
        __syncthreads();

        const uint32_t khb = sb + AKV_BASE + (it & 1) * AKV_BUF;
        const uint32_t klb = khb + AKV_TILE;
        const uint32_t vhb = khb + 2 * AKV_TILE;
        const uint32_t vlb = khb + 3 * AKV_TILE;

        float s[8][4];
#pragma unroll
        for (int ni = 0; ni < 8; ni++) {
            s[ni][0] = 0.f; s[ni][1] = 0.f; s[ni][2] = 0.f; s[ni][3] = 0.f;
        }
#pragma unroll
        for (int ks = 0; ks < 8; ks++) {
            uint32_t aQh[4], aQl[4];
            const int qrow = 16 * w + (lane & 15);
            const int qcc = ks * 2 + (lane >> 4);
            const uint32_t qoff = qrow * 256 + (((qcc ^ (qrow & 7))) << 4);
            ldsm4(aQh, sb + qoff);
            ldsm4(aQl, sb + AQ_BYTES + qoff);
#pragma unroll
            for (int np = 0; np < 4; np++) {
                uint32_t bKh[4], bKl[4];
                const int krow = np * 16 + ((lane >> 4) << 3) + (lane & 7);
                const int kcc = ks * 2 + ((lane >> 3) & 1);
                const uint32_t koff = krow * 256 + (((kcc ^ (krow & 7))) << 4);
                ldsm4(bKh, khb + koff);
                ldsm4(bKl, klb + koff);
                mma_bf16(s[2 * np],     aQh, bKh);
                mma_bf16(s[2 * np],     aQh, bKl);
                mma_bf16(s[2 * np],     aQl, bKh);
                mma_bf16(s[2 * np + 1], aQh, bKh + 2);
                mma_bf16(s[2 * np + 1], aQh, bKl + 2);
                mma_bf16(s[2 * np + 1], aQl, bKh + 2);
            }
        }

        float mx0 = -1e30f, mx1 = -1e30f;
#pragma unroll
        for (int ni = 0; ni < 8; ni++) {
            mx0 = fmaxf(mx0, fmaxf(s[ni][0], s[ni][1]));
            mx1 = fmaxf(mx1, fmaxf(s[ni][2], s[ni][3]));
        }
        mx0 = fmaxf(mx0, __shfl_xor_sync(0xffffffffu, mx0, 1));
        mx0 = fmaxf(mx0, __shfl_xor_sync(0xffffffffu, mx0, 2));
        mx1 = fmaxf(mx1, __shfl_xor_sync(0xffffffffu, mx1, 1));
        mx1 = fmaxf(mx1, __shfl_xor_sync(0xffffffffu, mx1, 2));
        const float mn0 = fmaxf(m0, mx0), mn1 = fmaxf(m1, mx1);
        const float c0 = __expf(m0 - mn0), c1 = __expf(m1 - mn1);
        m0 = mn0; m1 = mn1;
        float r0s = 0.f, r1s = 0.f;
#pragma unroll
        for (int ni = 0; ni < 8; ni++) {
            s[ni][0] = __expf(s[ni][0] - mn0);
            s[ni][1] = __expf(s[ni][1] - mn0);
            s[ni][2] = __expf(s[ni][2] - mn1);
            s[ni][3] = __expf(s[ni][3] - mn1);
            r0s += s[ni][0] + s[ni][1];
            r1s += s[ni][2] + s[ni][3];
        }
        l0 = l0 * c0 + r0s;
        l1 = l1 * c1 + r1s;
#pragma unroll
        for (int ni = 0; ni < 16; ni++) {
            o[ni][0] *= c0; o[ni][1] *= c0; o[ni][2] *= c1; o[ni][3] *= c1;
        }

#pragma unroll
        for (int t = 0; t < 4; t++) {
            uint32_t aPh[4], aPl[4];
            aPh[0] = pk2(s[2 * t][0], s[2 * t][1]);
            aPh[1] = pk2(s[2 * t][2], s[2 * t][3]);
            aPh[2] = pk2(s[2 * t + 1][0], s[2 * t + 1][1]);
            aPh[3] = pk2(s[2 * t + 1][2], s[2 * t + 1][3]);
            aPl[0] = pk2(bf16res(s[2 * t][0]), bf16res(s[2 * t][1]));
            aPl[1] = pk2(bf16res(s[2 * t][2]), bf16res(s[2 * t][3]));
            aPl[2] = pk2(bf16res(s[2 * t + 1][0]), bf16res(s[2 * t + 1][1]));
            aPl[3] = pk2(bf16res(s[2 * t + 1][2]), bf16res(s[2 * t + 1][3]));
#pragma unroll
            for (int np = 0; np < 8; np++) {
                uint32_t bVh[4], bVl[4];
                const int vrow = t * 16 + (lane & 7) + ((lane >> 3) & 1) * 8;
                const int vcc = np * 2 + (lane >> 4);
                const uint32_t voff = vrow * 256 + (((vcc ^ (vrow & 7))) << 4);
                ldsm4t(bVh, vhb + voff);
                ldsm4t(bVl, vlb + voff);
                mma_bf16(o[2 * np],     aPh, bVh);
                mma_bf16(o[2 * np],     aPh, bVl);
                mma_bf16(o[2 * np],     aPl, bVh);
                mma_bf16(o[2 * np + 1], aPh, bVh + 2);
                mma_bf16(o[2 * np + 1], aPh, bVl + 2);
                mma_bf16(o[2 * np + 1], aPl, bVh + 2);
            }
        }
        __syncthreads();
    }

    float lt0 = l0, lt1 = l1;
    lt0 += __shfl_xor_sync(0xffffffffu, lt0, 1);
    lt0 += __shfl_xor_sync(0xffffffffu, lt0, 2);
    lt1 += __shfl_xor_sync(0xffffffffu, lt1, 1);
    lt1 += __shfl_xor_sync(0xffffffffu, lt1, 2);
    const float inv0 = 1.f / lt0, inv1 = 1.f / lt1;

    const int b = bh >> 4, h = bh & 15;
    const int r = lane >> 2, cpp = (lane & 3) * 2;
    const int qr0 = q0 + 16 * w + r, qr1 = qr0 + 8;
#pragma unroll
    for (int ni = 0; ni < 16; ni++) {
        const int d = ni * 8 + cpp;
        const size_t i0 = ((size_t)(b * SEQ + qr0)) * D_MODEL + h * HEAD_DIM + d;
        const size_t i1 = ((size_t)(b * SEQ + qr1)) * D_MODEL + h * HEAD_DIM + d;
        float f0 = o[ni][0] * inv0, f1 = o[ni][1] * inv0;
        float f2 = o[ni][2] * inv1, f3 = o[ni][3] * inv1;
        *(uint32_t*)&ch[i0] = pk2(f0, f1);
        *(uint32_t*)&cl[i0] = pk2(bf16res(f0), bf16res(f1));
        *(uint32_t*)&ch[i1] = pk2(f2, f3);
        *(uint32_t*)&cl[i1] = pk2(bf16res(f2), bf16res(f3));
    }
}

// ============================================================
extern "C" void kernel_launch(void* const* d_in, const int* in_sizes, int n_in,
                              void* d_out, int out_size)
{
    const float* x  = (const float*)d_in[0];
    const float* wq = (const float*)d_in[1];
    const float* bq = (const float*)d_in[2];
    const float* wk = (const float*)d_in[3];
    const float* bk = (const float*)d_in[4];
    const float* wv = (const float*)d_in[5];
    const float* bv = (const float*)d_in[6];
    const float* wo = (const float*)d_in[7];
    const float* bo = (const float*)d_in[8];
    float* out = (float*)d_out;

    __nv_bfloat16 *xh, *xl, *wh, *wl, *ch, *cl, *qh, *ql, *kh, *kl, *vh, *vl;
    cudaGetSymbolAddress((void**)&xh, g_xh);
    cudaGetSymbolAddress((void**)&xl, g_xl);
    cudaGetSymbolAddress((void**)&wh, g_wh);
    cudaGetSymbolAddress((void**)&wl, g_wl);
    cudaGetSymbolAddress((void**)&ch, g_ch);
    cudaGetSymbolAddress((void**)&cl, g_cl);
    cudaGetSymbolAddress((void**)&qh, g_qh);
    cudaGetSymbolAddress((void**)&ql, g_ql);
    cudaGetSymbolAddress((void**)&kh, g_kh);
    cudaGetSymbolAddress((void**)&kl, g_kl);
    cudaGetSymbolAddress((void**)&vh, g_vh);
    cudaGetSymbolAddress((void**)&vl, g_vl);

    const size_t WN = (size_t)D_MODEL * D_MODEL;
    const int xn4 = (int)((size_t)MROWS * D_MODEL / 4);
    const int wn4 = (int)(WN / 4);

    split_kernel<<<(xn4 + 255) / 256, 256>>>(x, xh, xl, xn4);
    split_w4<<<dim3((wn4 + 255) / 256, 4), 256>>>(wq, wk, wv, wo, wh, wl, wn4);

    const int gsmem = 2 * BUFB;   // 147456
    cudaFuncSetAttribute(gemm_tc, cudaFuncAttributeMaxDynamicSharedMemorySize, gsmem);
    const dim3 ggrid(D_MODEL / 128, MROWS / 128);

    gemm_tc<<<ggrid, 256, gsmem>>>(xh, xl, wh + 0 * WN, wl + 0 * WN, bq,
                                   nullptr, qh, ql, 1, QSCALE);
    gemm_tc<<<ggrid, 256, gsmem>>>(xh, xl, wh + 1 * WN, wl + 1 * WN, bk,
                                   nullptr, kh, kl, 1, 1.0f);
    gemm_tc<<<ggrid, 256, gsmem>>>(xh, xl, wh + 2 * WN, wl + 2 * WN, bv,
                                   nullptr, vh, vl, 1, 1.0f);

    cudaFuncSetAttribute(attn_tc, cudaFuncAttributeMaxDynamicSharedMemorySize, ASMEM);
    attn_tc<<<dim3(SEQ / ABQ, BATCH * NUM_HEADS), 256, ASMEM>>>(qh, ql, kh, kl, vh, vl, ch, cl);

    gemm_tc<<<ggrid, 256, gsmem>>>(ch, cl, wh + 3 * WN, wl + 3 * WN, bo,
                                   out, nullptr, nullptr, 0, 1.0f);
}

// round 6
// speedup vs baseline: 3.9039x; 1.1566x over previous
#include <cuda_runtime.h>
#include <cuda_bf16.h>
#include <cuda_fp16.h>
#include <cstdint>
#include <math.h>

#define D_MODEL 2048
#define NUM_HEADS 16
#define HEAD_DIM 128
#define BATCH 2
#define SEQ 2048
#define MROWS (BATCH*SEQ)
#define GK 2048
#define QSCALE 0.0883883476483184f   // 1/sqrt(128)

// ---------------- scratch (static; no allocations allowed) ----------------
#define QKV_ELEMS ((size_t)BATCH*NUM_HEADS*SEQ*HEAD_DIM)
__device__ __align__(256) __nv_bfloat16 g_qh[QKV_ELEMS];
__device__ __align__(256) __nv_bfloat16 g_ql[QKV_ELEMS];
__device__ __align__(256) __nv_bfloat16 g_kh[QKV_ELEMS];
__device__ __align__(256) __nv_bfloat16 g_kl[QKV_ELEMS];
__device__ __align__(256) __half        g_vf[QKV_ELEMS];
__device__ __align__(256) __nv_bfloat16 g_xh[(size_t)MROWS*D_MODEL];
__device__ __align__(256) __nv_bfloat16 g_xl[(size_t)MROWS*D_MODEL];
__device__ __align__(256) __nv_bfloat16 g_wh[4][(size_t)D_MODEL*D_MODEL];
__device__ __align__(256) __nv_bfloat16 g_wl[4][(size_t)D_MODEL*D_MODEL];
__device__ __align__(256) __nv_bfloat16 g_ch[(size_t)MROWS*D_MODEL];
__device__ __align__(256) __nv_bfloat16 g_cl[(size_t)MROWS*D_MODEL];

// ---------------- helpers ----------------
__device__ __forceinline__ uint32_t smem_to_u32(const void* p) {
    uint32_t a;
    asm("{ .reg .u64 t; cvta.to.shared.u64 t, %1; cvt.u32.u64 %0, t; }" : "=r"(a) : "l"(p));
    return a;
}
__device__ __forceinline__ void ldsm4(uint32_t* r, uint32_t addr) {
    asm volatile("ldmatrix.sync.aligned.m8n8.x4.shared.b16 {%0,%1,%2,%3}, [%4];"
                 : "=r"(r[0]), "=r"(r[1]), "=r"(r[2]), "=r"(r[3]) : "r"(addr));
}
__device__ __forceinline__ void ldsm4t(uint32_t* r, uint32_t addr) {
    asm volatile("ldmatrix.sync.aligned.m8n8.x4.trans.shared.b16 {%0,%1,%2,%3}, [%4];"
                 : "=r"(r[0]), "=r"(r[1]), "=r"(r[2]), "=r"(r[3]) : "r"(addr));
}
__device__ __forceinline__ void mma_bf16(float* c, const uint32_t* a, const uint32_t* b) {
    asm volatile(
        "mma.sync.aligned.m16n8k16.row.col.f32.bf16.bf16.f32 "
        "{%0,%1,%2,%3}, {%4,%5,%6,%7}, {%8,%9}, {%0,%1,%2,%3};"
        : "+f"(c[0]), "+f"(c[1]), "+f"(c[2]), "+f"(c[3])
        : "r"(a[0]), "r"(a[1]), "r"(a[2]), "r"(a[3]), "r"(b[0]), "r"(b[1]));
}
__device__ __forceinline__ void mma_f16(float* c, const uint32_t* a, const uint32_t* b) {
    asm volatile(
        "mma.sync.aligned.m16n8k16.row.col.f32.f16.f16.f32 "
        "{%0,%1,%2,%3}, {%4,%5,%6,%7}, {%8,%9}, {%0,%1,%2,%3};"
        : "+f"(c[0]), "+f"(c[1]), "+f"(c[2]), "+f"(c[3])
        : "r"(a[0]), "r"(a[1]), "r"(a[2]), "r"(a[3]), "r"(b[0]), "r"(b[1]));
}
__device__ __forceinline__ void cp16(uint32_t saddr, const void* gaddr) {
    asm volatile("cp.async.cg.shared.global [%0], [%1], 16;" :: "r"(saddr), "l"(gaddr));
}
#define CP_COMMIT() asm volatile("cp.async.commit_group;")
#define CP_WAIT(n)  asm volatile("cp.async.wait_group %0;" :: "n"(n))

__device__ __forceinline__ uint32_t pk2(float x0, float x1) {
    uint32_t r;
    asm("cvt.rn.bf16x2.f32 %0, %1, %2;" : "=r"(r) : "f"(x1), "f"(x0));
    return r;
}
__device__ __forceinline__ uint32_t pkh2(float x0, float x1) {
    __half2 h = __floats2half2_rn(x0, x1);
    return *(uint32_t*)&h;
}
__device__ __forceinline__ float bf16res(float x) {
    return x - __bfloat162float(__float2bfloat16(x));
}

// ---------------- split fp32 -> bf16 hi/lo ----------------
__global__ __launch_bounds__(256)
void split_kernel(const float* __restrict__ in, __nv_bfloat16* __restrict__ hi,
                  __nv_bfloat16* __restrict__ lo, int n4)
{
    int i = blockIdx.x * blockDim.x + threadIdx.x;
    if (i >= n4) return;
    float4 v = ((const float4*)in)[i];
    ((uint32_t*)hi)[2 * i]     = pk2(v.x, v.y);
    ((uint32_t*)hi)[2 * i + 1] = pk2(v.z, v.w);
    ((uint32_t*)lo)[2 * i]     = pk2(bf16res(v.x), bf16res(v.y));
    ((uint32_t*)lo)[2 * i + 1] = pk2(bf16res(v.z), bf16res(v.w));
}

__global__ __launch_bounds__(256)
void split_w4(const float* __restrict__ w0, const float* __restrict__ w1,
              const float* __restrict__ w2, const float* __restrict__ w3,
              __nv_bfloat16* __restrict__ hi, __nv_bfloat16* __restrict__ lo, int n4)
{
    const float* ws[4] = {w0, w1, w2, w3};
    const float* in = ws[blockIdx.y];
    __nv_bfloat16* h = hi + (size_t)blockIdx.y * D_MODEL * D_MODEL;
    __nv_bfloat16* l = lo + (size_t)blockIdx.y * D_MODEL * D_MODEL;
    int i = blockIdx.x * blockDim.x + threadIdx.x;
    if (i >= n4) return;
    float4 v = ((const float4*)in)[i];
    ((uint32_t*)h)[2 * i]     = pk2(v.x, v.y);
    ((uint32_t*)h)[2 * i + 1] = pk2(v.z, v.w);
    ((uint32_t*)l)[2 * i]     = pk2(bf16res(v.x), bf16res(v.y));
    ((uint32_t*)l)[2 * i + 1] = pk2(bf16res(v.z), bf16res(v.w));
}

// ---------------- mma.sync split-bf16 GEMM ----------------
// mode 0: C = A@W^T + bias -> fp32 row-major (final projection)
// mode 1: fused QKV. blockIdx.x spans N=6144 (wq|wk|wv rows contiguous in g_wh).
//         proj 0 -> Q bf16 hi/lo scaled by QSCALE; proj 1 -> K bf16 hi/lo; proj 2 -> V fp16.
#define BKC 64
#define ROWB 144
#define TILE_BYTES (128*ROWB)
#define BUFB (4*TILE_BYTES)
#define NCH (GK/BKC)

__device__ __forceinline__ void load_chunk(uint32_t sbase,
                                           const __nv_bfloat16* g0, const __nv_bfloat16* g1,
                                           const __nv_bfloat16* g2, const __nv_bfloat16* g3,
                                           int k0, int tid)
{
    const __nv_bfloat16* gp[4] = {g0, g1, g2, g3};
#pragma unroll
    for (int t = 0; t < 16; t++) {
        const int id = tid + t * 256;
        const int tile = id >> 10;
        const int idx = id & 1023;
        const int row = idx >> 3;
        const int c = idx & 7;
        uint32_t sa = sbase + tile * TILE_BYTES + row * ROWB + c * 16;
        const __nv_bfloat16* ga = gp[tile] + (size_t)row * GK + k0 + c * 8;
        cp16(sa, ga);
    }
    CP_COMMIT();
}

__global__ __launch_bounds__(256, 1)
void gemm_tc(const __nv_bfloat16* __restrict__ Ah, const __nv_bfloat16* __restrict__ Al,
             const __nv_bfloat16* __restrict__ Wh, const __nv_bfloat16* __restrict__ Wl,
             const float* __restrict__ b0p, const float* __restrict__ b1p,
             const float* __restrict__ b2p,
             float* __restrict__ outf,
             __nv_bfloat16* __restrict__ oqh, __nv_bfloat16* __restrict__ oql,
             __nv_bfloat16* __restrict__ okh, __nv_bfloat16* __restrict__ okl,
             __half* __restrict__ ovf, int mode)
{
    extern __shared__ char smem[];
    const uint32_t sb = smem_to_u32(smem);
    const int tid = threadIdx.x;
    const int lane = tid & 31;
    const int wid = tid >> 5;
    const int wm = wid >> 2;
    const int wn = wid & 3;
    const int n0 = blockIdx.x * 128;
    const int m0 = blockIdx.y * 128;

    const __nv_bfloat16* a_h = Ah + (size_t)m0 * GK;
    const __nv_bfloat16* a_l = Al + (size_t)m0 * GK;
    const __nv_bfloat16* b_h = Wh + (size_t)n0 * GK;
    const __nv_bfloat16* b_l = Wl + (size_t)n0 * GK;

    float acc[4][4][4];
#pragma unroll
    for (int mi = 0; mi < 4; mi++)
#pragma unroll
        for (int ni = 0; ni < 4; ni++)
#pragma unroll
            for (int e = 0; e < 4; e++) acc[mi][ni][e] = 0.f;

    load_chunk(sb, a_h, a_l, b_h, b_l, 0, tid);

    const int arow = wm * 64 + (lane & 15);
    const uint32_t aoff0 = (lane >> 4) * 16;
    const int brow = wn * 32 + ((lane >> 4) << 3) + (lane & 7);
    const uint32_t boff0 = ((lane >> 3) & 1) * 16;

    for (int ch = 0; ch < NCH; ch++) {
        CP_WAIT(0);
        __syncthreads();
        if (ch + 1 < NCH)
            load_chunk(sb + ((ch + 1) & 1) * BUFB, a_h, a_l, b_h, b_l, (ch + 1) * BKC, tid);

        const uint32_t base = sb + (ch & 1) * BUFB;
        const uint32_t aBaseH = base;
        const uint32_t aBaseL = base + TILE_BYTES;
        const uint32_t bBaseH = base + 2 * TILE_BYTES;
        const uint32_t bBaseL = base + 3 * TILE_BYTES;

#pragma unroll
        for (int kk = 0; kk < 4; kk++) {
            uint32_t ah[4][4], al[4][4], bh[2][4], bl[2][4];
            const uint32_t aoff = aoff0 + kk * 32;
#pragma unroll
            for (int mi = 0; mi < 4; mi++) {
                ldsm4(ah[mi], aBaseH + (arow + mi * 16) * ROWB + aoff);
                ldsm4(al[mi], aBaseL + (arow + mi * 16) * ROWB + aoff);
            }
            const uint32_t boff = boff0 + kk * 32;
#pragma unroll
            for (int p = 0; p < 2; p++) {
                ldsm4(bh[p], bBaseH + (brow + p * 16) * ROWB + boff);
                ldsm4(bl[p], bBaseL + (brow + p * 16) * ROWB + boff);
            }
#pragma unroll
            for (int mi = 0; mi < 4; mi++)
#pragma unroll
                for (int p = 0; p < 2; p++) {
                    mma_bf16(acc[mi][2 * p],     ah[mi], bh[p]);
                    mma_bf16(acc[mi][2 * p],     ah[mi], bl[p]);
                    mma_bf16(acc[mi][2 * p],     al[mi], bh[p]);
                    mma_bf16(acc[mi][2 * p + 1], ah[mi], bh[p] + 2);
                    mma_bf16(acc[mi][2 * p + 1], ah[mi], bl[p] + 2);
                    mma_bf16(acc[mi][2 * p + 1], al[mi], bh[p] + 2);
                }
        }
        __syncthreads();
    }

    const int r = lane >> 2;
    const int cp = (lane & 3) * 2;
    const int mbase = m0 + wm * 64;
    const int nbase = n0 + wn * 32;

    const int proj = n0 >> 11;
    const float* bias = (mode == 0) ? b0p : (proj == 0 ? b0p : (proj == 1 ? b1p : b2p));
    const float scl = (mode == 1 && proj == 0) ? QSCALE : 1.0f;

#pragma unroll
    for (int mi = 0; mi < 4; mi++) {
#pragma unroll
        for (int ni = 0; ni < 4; ni++) {
            const int n_g = nbase + ni * 8 + cp;
            const float b0v = bias[(mode == 0) ? n_g : (n_g & 2047)],
                        b1v = bias[((mode == 0) ? n_g : (n_g & 2047)) + 1];
            const int m0g = mbase + mi * 16 + r;
            const int m1g = m0g + 8;
            float v0x = (acc[mi][ni][0] + b0v) * scl;
            float v0y = (acc[mi][ni][1] + b1v) * scl;
            float v1x = (acc[mi][ni][2] + b0v) * scl;
            float v1y = (acc[mi][ni][3] + b1v) * scl;
            if (mode == 0) {
                float2 v0 = {v0x, v0y}, v1 = {v1x, v1y};
                *(float2*)&outf[(size_t)m0g * D_MODEL + n_g] = v0;
                *(float2*)&outf[(size_t)m1g * D_MODEL + n_g] = v1;
            } else {
                const int h = (n_g >> 7) & 15;
                const int d = n_g & 127;
                const int b0i = m0g >> 11, s0 = m0g & 2047;
                const int b1i = m1g >> 11, s1 = m1g & 2047;
                const size_t i0 = (((size_t)(b0i * NUM_HEADS + h) * SEQ + s0) * HEAD_DIM) + d;
                const size_t i1 = (((size_t)(b1i * NUM_HEADS + h) * SEQ + s1) * HEAD_DIM) + d;
                if (proj == 0) {
                    *(uint32_t*)&oqh[i0] = pk2(v0x, v0y);
                    *(uint32_t*)&oql[i0] = pk2(bf16res(v0x), bf16res(v0y));
                    *(uint32_t*)&oqh[i1] = pk2(v1x, v1y);
                    *(uint32_t*)&oql[i1] = pk2(bf16res(v1x), bf16res(v1y));
                } else if (proj == 1) {
                    *(uint32_t*)&okh[i0] = pk2(v0x, v0y);
                    *(uint32_t*)&okl[i0] = pk2(bf16res(v0x), bf16res(v0y));
                    *(uint32_t*)&okh[i1] = pk2(v1x, v1y);
                    *(uint32_t*)&okl[i1] = pk2(bf16res(v1x), bf16res(v1y));
                } else {
                    *(uint32_t*)&ovf[i0] = pkh2(v0x, v0y);
                    *(uint32_t*)&ovf[i1] = pkh2(v1x, v1y);
                }
            }
        }
    }
}

// ============================================================
// Flash attention: QK^T 3-term split bf16; PV single fp16 mma.
// ============================================================
#define ABQ 128
#define ABKV 64
#define AQ_BYTES 32768
#define AKV_TILE 16384
#define AKV_BUF  (3*AKV_TILE)       // Kh, Kl, Vf
#define AKV_BASE (2*AQ_BYTES)
#define ASMEM (AKV_BASE + 2*AKV_BUF)   // 163840

__device__ __forceinline__ void attn_load_kv(uint32_t sbuf,
    const __nv_bfloat16* kh_, const __nv_bfloat16* kl_, const __half* vf_,
    int kv0, int tid)
{
    const void* gp[3] = {kh_, kl_, vf_};
#pragma unroll
    for (int i = 0; i < 12; i++) {
        int id = i * 256 + tid;
        int tile = id >> 10;
        int idx = id & 1023;
        int row = idx >> 4;
        int cc = idx & 15;
        uint32_t dst = sbuf + tile * AKV_TILE + row * 256 + (((cc ^ (row & 7))) << 4);
        const char* src = (const char*)gp[tile] + ((size_t)(kv0 + row) * HEAD_DIM + cc * 8) * 2;
        cp16(dst, src);
    }
    CP_COMMIT();
}

__global__ __launch_bounds__(256, 1)
void attn_tc(const __nv_bfloat16* __restrict__ qh, const __nv_bfloat16* __restrict__ ql,
             const __nv_bfloat16* __restrict__ kh, const __nv_bfloat16* __restrict__ kl,
             const __half* __restrict__ vf,
             __nv_bfloat16* __restrict__ ch, __nv_bfloat16* __restrict__ cl)
{
    extern __shared__ char smem[];
    const uint32_t sb = smem_to_u32(smem);
    const int tid = threadIdx.x;
    const int lane = tid & 31;
    const int w = tid >> 5;
    const int bh = blockIdx.y;
    const int q0 = blockIdx.x * ABQ;
    const size_t base = (size_t)bh * SEQ * HEAD_DIM;

    {
        const __nv_bfloat16* gq[2] = {qh + base, ql + base};
#pragma unroll
        for (int i = 0; i < 16; i++) {
            int id = i * 256 + tid;
            int tile = id >> 11;
            int idx = id & 2047;
            int row = idx >> 4;
            int cc = idx & 15;
            uint32_t dst = sb + tile * AQ_BYTES + row * 256 + (((cc ^ (row & 7))) << 4);
            cp16(dst, gq[tile] + (size_t)(q0 + row) * HEAD_DIM + cc * 8);
        }
        CP_COMMIT();
    }
    attn_load_kv(sb + AKV_BASE, kh + base, kl + base, vf + base, 0, tid);

    float o[16][4];
#pragma unroll
    for (int ni = 0; ni < 16; ni++)
#pragma unroll
        for (int e = 0; e < 4; e++) o[ni][e] = 0.f;
    float m0 = -1e30f, m1 = -1e30f, l0 = 0.f, l1 = 0.f;

    const int NKV = SEQ / ABKV;
    for (int it = 0; it < NKV; it++) {
        CP_WAIT(0);
        __syncthreads();
        if (it + 1 < NKV)
            attn_load_kv(sb + AKV_BASE + ((it + 1) & 1) * AKV_BUF,
                         kh + base, kl + base, vf + base, (it + 1) * ABKV, tid);

        const uint32_t khb = sb + AKV_BASE + (it & 1) * AKV_BUF;
        const uint32_t klb = khb + AKV_TILE;
        const uint32_t vhb = khb + 2 * AKV_TILE;

        float s[8][4];
#pragma unroll
        for (int ni = 0; ni < 8; ni++) {
            s[ni][0] = 0.f; s[ni][1] = 0.f; s[ni][2] = 0.f; s[ni][3] = 0.f;
        }
#pragma unroll
        for (int ks = 0; ks < 8; ks++) {
            uint32_t aQh[4], aQl[4];
            const int qrow = 16 * w + (lane & 15);
            const int qcc = ks * 2 + (lane >> 4);
            const uint32_t qoff = qrow * 256 + (((qcc ^ (qrow & 7))) << 4);
            ldsm4(aQh, sb + qoff);
            ldsm4(aQl, sb + AQ_BYTES + qoff);
#pragma unroll
            for (int np = 0; np < 4; np++) {
                uint32_t bKh[4], bKl[4];
                const int krow = np * 16 + ((lane >> 4) << 3) + (lane & 7);
                const int kcc = ks * 2 + ((lane >> 3) & 1);
                const uint32_t koff = krow * 256 + (((kcc ^ (krow & 7))) << 4);
                ldsm4(bKh, khb + koff);
                ldsm4(bKl, klb + koff);
                mma_bf16(s[2 * np],     aQh, bKh);
                mma_bf16(s[2 * np],     aQh, bKl);
                mma_bf16(s[2 * np],     aQl, bKh);
                mma_bf16(s[2 * np + 1], aQh, bKh + 2);
                mma_bf16(s[2 * np + 1], aQh, bKl + 2);
                mma_bf16(s[2 * np + 1], aQl, bKh + 2);
            }
        }

        float mx0 = -1e30f, mx1 = -1e30f;
#pragma unroll
        for (int ni = 0; ni < 8; ni++) {
            mx0 = fmaxf(mx0, fmaxf(s[ni][0], s[ni][1]));
            mx1 = fmaxf(mx1, fmaxf(s[ni][2], s[ni][3]));
        }
        mx0 = fmaxf(mx0, __shfl_xor_sync(0xffffffffu, mx0, 1));
        mx0 = fmaxf(mx0, __shfl_xor_sync(0xffffffffu, mx0, 2));
        mx1 = fmaxf(mx1, __shfl_xor_sync(0xffffffffu, mx1, 1));
        mx1 = fmaxf(mx1, __shfl_xor_sync(0xffffffffu, mx1, 2));
        const float mn0 = fmaxf(m0, mx0), mn1 = fmaxf(m1, mx1);
        const float c0 = __expf(m0 - mn0), c1 = __expf(m1 - mn1);
        m0 = mn0; m1 = mn1;
        float r0s = 0.f, r1s = 0.f;
#pragma unroll
        for (int ni = 0; ni < 8; ni++) {
            s[ni][0] = __expf(s[ni][0] - mn0);
            s[ni][1] = __expf(s[ni][1] - mn0);
            s[ni][2] = __expf(s[ni][2] - mn1);
            s[ni][3] = __expf(s[ni][3] - mn1);
            r0s += s[ni][0] + s[ni][1];
            r1s += s[ni][2] + s[ni][3];
        }
        l0 = l0 * c0 + r0s;
        l1 = l1 * c1 + r1s;
#pragma unroll
        for (int ni = 0; ni < 16; ni++) {
            o[ni][0] *= c0; o[ni][1] *= c0; o[ni][2] *= c1; o[ni][3] *= c1;
        }

        // O += P V : single fp16 mma term
#pragma unroll
        for (int t = 0; t < 4; t++) {
            uint32_t aP[4];
            aP[0] = pkh2(s[2 * t][0], s[2 * t][1]);
            aP[1] = pkh2(s[2 * t][2], s[2 * t][3]);
            aP[2] = pkh2(s[2 * t + 1][0], s[2 * t + 1][1]);
            aP[3] = pkh2(s[2 * t + 1][2], s[2 * t + 1][3]);
#pragma unroll
            for (int np = 0; np < 8; np++) {
                uint32_t bV[4];
                const int vrow = t * 16 + (lane & 7) + ((lane >> 3) & 1) * 8;
                const int vcc = np * 2 + (lane >> 4);
                const uint32_t voff = vrow * 256 + (((vcc ^ (vrow & 7))) << 4);
                ldsm4t(bV, vhb + voff);
                mma_f16(o[2 * np],     aP, bV);
                mma_f16(o[2 * np + 1], aP, bV + 2);
            }
        }
        __syncthreads();
    }

    float lt0 = l0, lt1 = l1;
    lt0 += __shfl_xor_sync(0xffffffffu, lt0, 1);
    lt0 += __shfl_xor_sync(0xffffffffu, lt0, 2);
    lt1 += __shfl_xor_sync(0xffffffffu, lt1, 1);
    lt1 += __shfl_xor_sync(0xffffffffu, lt1, 2);
    const float inv0 = 1.f / lt0, inv1 = 1.f / lt1;

    const int b = bh >> 4, h = bh & 15;
    const int r = lane >> 2, cpp = (lane & 3) * 2;
    const int qr0 = q0 + 16 * w + r, qr1 = qr0 + 8;
#pragma unroll
    for (int ni = 0; ni < 16; ni++) {
        const int d = ni * 8 + cpp;
        const size_t i0 = ((size_t)(b * SEQ + qr0)) * D_MODEL + h * HEAD_DIM + d;
        const size_t i1 = ((size_t)(b * SEQ + qr1)) * D_MODEL + h * HEAD_DIM + d;
        float f0 = o[ni][0] * inv0, f1 = o[ni][1] * inv0;
        float f2 = o[ni][2] * inv1, f3 = o[ni][3] * inv1;
        *(uint32_t*)&ch[i0] = pk2(f0, f1);
        *(uint32_t*)&cl[i0] = pk2(bf16res(f0), bf16res(f1));
        *(uint32_t*)&ch[i1] = pk2(f2, f3);
        *(uint32_t*)&cl[i1] = pk2(bf16res(f2), bf16res(f3));
    }
}

// ============================================================
extern "C" void kernel_launch(void* const* d_in, const int* in_sizes, int n_in,
                              void* d_out, int out_size)
{
    const float* x  = (const float*)d_in[0];
    const float* wq = (const float*)d_in[1];
    const float* bq = (const float*)d_in[2];
    const float* wk = (const float*)d_in[3];
    const float* bk = (const float*)d_in[4];
    const float* wv = (const float*)d_in[5];
    const float* bv = (const float*)d_in[6];
    const float* wo = (const float*)d_in[7];
    const float* bo = (const float*)d_in[8];
    float* out = (float*)d_out;

    __nv_bfloat16 *xh, *xl, *wh, *wl, *ch, *cl, *qh, *ql, *kh, *kl;
    __half* vf;
    cudaGetSymbolAddress((void**)&xh, g_xh);
    cudaGetSymbolAddress((void**)&xl, g_xl);
    cudaGetSymbolAddress((void**)&wh, g_wh);
    cudaGetSymbolAddress((void**)&wl, g_wl);
    cudaGetSymbolAddress((void**)&ch, g_ch);
    cudaGetSymbolAddress((void**)&cl, g_cl);
    cudaGetSymbolAddress((void**)&qh, g_qh);
    cudaGetSymbolAddress((void**)&ql, g_ql);
    cudaGetSymbolAddress((void**)&kh, g_kh);
    cudaGetSymbolAddress((void**)&kl, g_kl);
    cudaGetSymbolAddress((void**)&vf, g_vf);

    const size_t WN = (size_t)D_MODEL * D_MODEL;
    const int xn4 = (int)((size_t)MROWS * D_MODEL / 4);
    const int wn4 = (int)(WN / 4);

    split_kernel<<<(xn4 + 255) / 256, 256>>>(x, xh, xl, xn4);
    split_w4<<<dim3((wn4 + 255) / 256, 4), 256>>>(wq, wk, wv, wo, wh, wl, wn4);

    const int gsmem = 2 * BUFB;
    cudaFuncSetAttribute(gemm_tc, cudaFuncAttributeMaxDynamicSharedMemorySize, gsmem);

    // fused QKV: N spans wq|wk|wv rows (contiguous in g_wh/g_wl)
    gemm_tc<<<dim3(3 * D_MODEL / 128, MROWS / 128), 256, gsmem>>>(
        xh, xl, wh, wl, bq, bk, bv,
        nullptr, qh, ql, kh, kl, vf, 1);

    cudaFuncSetAttribute(attn_tc, cudaFuncAttributeMaxDynamicSharedMemorySize, ASMEM);
    attn_tc<<<dim3(SEQ / ABQ, BATCH * NUM_HEADS), 256, ASMEM>>>(qh, ql, kh, kl, vf, ch, cl);

    gemm_tc<<<dim3(D_MODEL / 128, MROWS / 128), 256, gsmem>>>(
        ch, cl, wh + 3 * WN, wl + 3 * WN, bo, nullptr, nullptr,
        out, nullptr, nullptr, nullptr, nullptr, nullptr, 0);
}

// round 8
// speedup vs baseline: 5.2755x; 1.3513x over previous
#include <cuda_runtime.h>
#include <cuda_fp16.h>
#include <cstdint>
#include <math.h>

#define D_MODEL 2048
#define NUM_HEADS 16
#define HEAD_DIM 128
#define BATCH 2
#define SEQ 2048
#define MROWS (BATCH*SEQ)
#define GK 2048
#define QSCALE 0.0883883476483184f   // 1/sqrt(128)

// ---------------- scratch (static; no allocations allowed) ----------------
#define QKV_ELEMS ((size_t)BATCH*NUM_HEADS*SEQ*HEAD_DIM)
__device__ __align__(256) __half g_qh[QKV_ELEMS];
__device__ __align__(256) __half g_ql[QKV_ELEMS];
__device__ __align__(256) __half g_kf[QKV_ELEMS];
__device__ __align__(256) __half g_vf[QKV_ELEMS];
__device__ __align__(256) __half g_xh[(size_t)MROWS*D_MODEL];
__device__ __align__(256) __half g_xl[(size_t)MROWS*D_MODEL];
__device__ __align__(256) __half g_wf[4][(size_t)D_MODEL*D_MODEL];
__device__ __align__(256) __half g_ch[(size_t)MROWS*D_MODEL];
__device__ __align__(256) __half g_cl[(size_t)MROWS*D_MODEL];

// ---------------- helpers ----------------
__device__ __forceinline__ uint32_t smem_to_u32(const void* p) {
    uint32_t a;
    asm("{ .reg .u64 t; cvta.to.shared.u64 t, %1; cvt.u32.u64 %0, t; }" : "=r"(a) : "l"(p));
    return a;
}
__device__ __forceinline__ void ldsm4(uint32_t* r, uint32_t addr) {
    asm volatile("ldmatrix.sync.aligned.m8n8.x4.shared.b16 {%0,%1,%2,%3}, [%4];"
                 : "=r"(r[0]), "=r"(r[1]), "=r"(r[2]), "=r"(r[3]) : "r"(addr));
}
__device__ __forceinline__ void ldsm4t(uint32_t* r, uint32_t addr) {
    asm volatile("ldmatrix.sync.aligned.m8n8.x4.trans.shared.b16 {%0,%1,%2,%3}, [%4];"
                 : "=r"(r[0]), "=r"(r[1]), "=r"(r[2]), "=r"(r[3]) : "r"(addr));
}
__device__ __forceinline__ void mma_f16(float* c, const uint32_t* a, const uint32_t* b) {
    asm volatile(
        "mma.sync.aligned.m16n8k16.row.col.f32.f16.f16.f32 "
        "{%0,%1,%2,%3}, {%4,%5,%6,%7}, {%8,%9}, {%0,%1,%2,%3};"
        : "+f"(c[0]), "+f"(c[1]), "+f"(c[2]), "+f"(c[3])
        : "r"(a[0]), "r"(a[1]), "r"(a[2]), "r"(a[3]), "r"(b[0]), "r"(b[1]));
}
__device__ __forceinline__ void cp16(uint32_t saddr, const void* gaddr) {
    asm volatile("cp.async.cg.shared.global [%0], [%1], 16;" :: "r"(saddr), "l"(gaddr));
}
#define CP_COMMIT() asm volatile("cp.async.commit_group;")
#define CP_WAIT(n)  asm volatile("cp.async.wait_group %0;" :: "n"(n))

__device__ __forceinline__ uint32_t pkh2(float x0, float x1) {
    __half2 h = __floats2half2_rn(x0, x1);
    return *(uint32_t*)&h;
}
__device__ __forceinline__ float hres(float x) {
    return x - __half2float(__float2half(x));
}

// ---------------- split fp32 -> fp16 hi/lo (activations) ----------------
__global__ __launch_bounds__(256)
void split_x(const float* __restrict__ in, __half* __restrict__ hi,
             __half* __restrict__ lo, int n4)
{
    int i = blockIdx.x * blockDim.x + threadIdx.x;
    if (i >= n4) return;
    float4 v = ((const float4*)in)[i];
    ((uint32_t*)hi)[2 * i]     = pkh2(v.x, v.y);
    ((uint32_t*)hi)[2 * i + 1] = pkh2(v.z, v.w);
    ((uint32_t*)lo)[2 * i]     = pkh2(hres(v.x), hres(v.y));
    ((uint32_t*)lo)[2 * i + 1] = pkh2(hres(v.z), hres(v.w));
}

// weights: fp16 hi only (4 matrices fused)
__global__ __launch_bounds__(256)
void split_w4(const float* __restrict__ w0, const float* __restrict__ w1,
              const float* __restrict__ w2, const float* __restrict__ w3,
              __half* __restrict__ hi, int n4)
{
    const float* ws[4] = {w0, w1, w2, w3};
    const float* in = ws[blockIdx.y];
    __half* h = hi + (size_t)blockIdx.y * D_MODEL * D_MODEL;
    int i = blockIdx.x * blockDim.x + threadIdx.x;
    if (i >= n4) return;
    float4 v = ((const float4*)in)[i];
    ((uint32_t*)h)[2 * i]     = pkh2(v.x, v.y);
    ((uint32_t*)h)[2 * i + 1] = pkh2(v.z, v.w);
}

// ---------------- fp16 2-term GEMM: C = (Ah+Al) @ Wf^T + bias ----------------
// CTA tile 128x128, BK=64, 8 warps (2x4), warp tile 64x32.
// SMEM: 3 tiles per chunk (Ah, Al, W), row stride 144B.
#define BKC 64
#define ROWB 144
#define TILE_BYTES (128*ROWB)       // 18432
#define BUFB (3*TILE_BYTES)         // 55296
#define NCH (GK/BKC)                // 32

__device__ __forceinline__ void load_chunk(uint32_t sbase,
                                           const __half* g0, const __half* g1,
                                           const __half* g2, int k0, int tid)
{
    const __half* gp[3] = {g0, g1, g2};
#pragma unroll
    for (int t = 0; t < 12; t++) {
        const int id = tid + t * 256;
        const int tile = id >> 10;
        const int idx = id & 1023;
        const int row = idx >> 3;
        const int c = idx & 7;
        uint32_t sa = sbase + tile * TILE_BYTES + row * ROWB + c * 16;
        const __half* ga = gp[tile] + (size_t)row * GK + k0 + c * 8;
        cp16(sa, ga);
    }
    CP_COMMIT();
}

// mode 0: fp32 row-major out (final projection)
// mode 1: fused QKV over N=6144: proj0 -> Q fp16 hi/lo (scaled), proj1 -> K fp16, proj2 -> V fp16
__global__ __launch_bounds__(256, 1)
void gemm_tc(const __half* __restrict__ Ah, const __half* __restrict__ Al,
             const __half* __restrict__ Wf,
             const float* __restrict__ b0p, const float* __restrict__ b1p,
             const float* __restrict__ b2p,
             float* __restrict__ outf,
             __half* __restrict__ oqh, __half* __restrict__ oql,
             __half* __restrict__ okf, __half* __restrict__ ovf, int mode)
{
    extern __shared__ char smem[];
    const uint32_t sb = smem_to_u32(smem);
    const int tid = threadIdx.x;
    const int lane = tid & 31;
    const int wid = tid >> 5;
    const int wm = wid >> 2;
    const int wn = wid & 3;
    const int n0 = blockIdx.x * 128;
    const int m0 = blockIdx.y * 128;

    const __half* a_h = Ah + (size_t)m0 * GK;
    const __half* a_l = Al + (size_t)m0 * GK;
    const __half* b_f = Wf + (size_t)n0 * GK;

    float acc[4][4][4];
#pragma unroll
    for (int mi = 0; mi < 4; mi++)
#pragma unroll
        for (int ni = 0; ni < 4; ni++)
#pragma unroll
            for (int e = 0; e < 4; e++) acc[mi][ni][e] = 0.f;

    load_chunk(sb, a_h, a_l, b_f, 0, tid);

    const int arow = wm * 64 + (lane & 15);
    const uint32_t aoff0 = (lane >> 4) * 16;
    const int brow = wn * 32 + ((lane >> 4) << 3) + (lane & 7);
    const uint32_t boff0 = ((lane >> 3) & 1) * 16;

    for (int ch = 0; ch < NCH; ch++) {
        CP_WAIT(0);
        __syncthreads();
        if (ch + 1 < NCH)
            load_chunk(sb + ((ch + 1) & 1) * BUFB, a_h, a_l, b_f, (ch + 1) * BKC, tid);

        const uint32_t base = sb + (ch & 1) * BUFB;
        const uint32_t aBaseH = base;
        const uint32_t aBaseL = base + TILE_BYTES;
        const uint32_t bBase  = base + 2 * TILE_BYTES;

#pragma unroll
        for (int kk = 0; kk < 4; kk++) {
            uint32_t ah[4][4], al[4][4], bf[2][4];
            const uint32_t aoff = aoff0 + kk * 32;
#pragma unroll
            for (int mi = 0; mi < 4; mi++) {
                ldsm4(ah[mi], aBaseH + (arow + mi * 16) * ROWB + aoff);
                ldsm4(al[mi], aBaseL + (arow + mi * 16) * ROWB + aoff);
            }
            const uint32_t boff = boff0 + kk * 32;
#pragma unroll
            for (int p = 0; p < 2; p++)
                ldsm4(bf[p], bBase + (brow + p * 16) * ROWB + boff);
#pragma unroll
            for (int mi = 0; mi < 4; mi++)
#pragma unroll
                for (int p = 0; p < 2; p++) {
                    mma_f16(acc[mi][2 * p],     ah[mi], bf[p]);
                    mma_f16(acc[mi][2 * p],     al[mi], bf[p]);
                    mma_f16(acc[mi][2 * p + 1], ah[mi], bf[p] + 2);
                    mma_f16(acc[mi][2 * p + 1], al[mi], bf[p] + 2);
                }
        }
        __syncthreads();
    }

    const int r = lane >> 2;
    const int cp = (lane & 3) * 2;
    const int mbase = m0 + wm * 64;
    const int nbase = n0 + wn * 32;

    const int proj = n0 >> 11;
    const float* bias = (mode == 0) ? b0p : (proj == 0 ? b0p : (proj == 1 ? b1p : b2p));
    const float scl = (mode == 1 && proj == 0) ? QSCALE : 1.0f;

#pragma unroll
    for (int mi = 0; mi < 4; mi++) {
#pragma unroll
        for (int ni = 0; ni < 4; ni++) {
            const int n_g = nbase + ni * 8 + cp;
            const int nb = (mode == 0) ? n_g : (n_g & 2047);
            const float b0v = bias[nb], b1v = bias[nb + 1];
            const int m0g = mbase + mi * 16 + r;
            const int m1g = m0g + 8;
            float v0x = (acc[mi][ni][0] + b0v) * scl;
            float v0y = (acc[mi][ni][1] + b1v) * scl;
            float v1x = (acc[mi][ni][2] + b0v) * scl;
            float v1y = (acc[mi][ni][3] + b1v) * scl;
            if (mode == 0) {
                float2 v0 = {v0x, v0y}, v1 = {v1x, v1y};
                *(float2*)&outf[(size_t)m0g * D_MODEL + n_g] = v0;
                *(float2*)&outf[(size_t)m1g * D_MODEL + n_g] = v1;
            } else {
                const int h = (n_g >> 7) & 15;
                const int d = n_g & 127;
                const int b0i = m0g >> 11, s0 = m0g & 2047;
                const int b1i = m1g >> 11, s1 = m1g & 2047;
                const size_t i0 = (((size_t)(b0i * NUM_HEADS + h) * SEQ + s0) * HEAD_DIM) + d;
                const size_t i1 = (((size_t)(b1i * NUM_HEADS + h) * SEQ + s1) * HEAD_DIM) + d;
                if (proj == 0) {
                    *(uint32_t*)&oqh[i0] = pkh2(v0x, v0y);
                    *(uint32_t*)&oql[i0] = pkh2(hres(v0x), hres(v0y));
                    *(uint32_t*)&oqh[i1] = pkh2(v1x, v1y);
                    *(uint32_t*)&oql[i1] = pkh2(hres(v1x), hres(v1y));
                } else if (proj == 1) {
                    *(uint32_t*)&okf[i0] = pkh2(v0x, v0y);
                    *(uint32_t*)&okf[i1] = pkh2(v1x, v1y);
                } else {
                    *(uint32_t*)&ovf[i0] = pkh2(v0x, v0y);
                    *(uint32_t*)&ovf[i1] = pkh2(v1x, v1y);
                }
            }
        }
    }
}

// ============================================================
// Flash attention: QK^T = (Qh+Ql)·Kf (2-term fp16); PV single fp16.
// ============================================================
#define ABQ 128
#define ABKV 64
#define AQ_BYTES 32768
#define AKV_TILE 16384
#define AKV_BUF  (2*AKV_TILE)          // Kf, Vf
#define AKV_BASE (2*AQ_BYTES)
#define ASMEM (AKV_BASE + 2*AKV_BUF)   // 131072

__device__ __forceinline__ void attn_load_kv(uint32_t sbuf,
    const __half* kf_, const __half* vf_, int kv0, int tid)
{
    const __half* gp[2] = {kf_, vf_};
#pragma unroll
    for (int i = 0; i < 8; i++) {
        int id = i * 256 + tid;
        int tile = id >> 10;
        int idx = id & 1023;
        int row = idx >> 4;
        int cc = idx & 15;
        uint32_t dst = sbuf + tile * AKV_TILE + row * 256 + (((cc ^ (row & 7))) << 4);
        cp16(dst, gp[tile] + (size_t)(kv0 + row) * HEAD_DIM + cc * 8);
    }
    CP_COMMIT();
}

__global__ __launch_bounds__(256, 1)
void attn_tc(const __half* __restrict__ qh, const __half* __restrict__ ql,
             const __half* __restrict__ kf, const __half* __restrict__ vf,
             __half* __restrict__ ch, __half* __restrict__ cl)
{
    extern __shared__ char smem[];
    const uint32_t sb = smem_to_u32(smem);
    const int tid = threadIdx.x;
    const int lane = tid & 31;
    const int w = tid >> 5;
    const int bh = blockIdx.y;
    const int q0 = blockIdx.x * ABQ;
    const size_t base = (size_t)bh * SEQ * HEAD_DIM;

    {
        const __half* gq[2] = {qh + base, ql + base};
#pragma unroll
        for (int i = 0; i < 16; i++) {
            int id = i * 256 + tid;
            int tile = id >> 11;
            int idx = id & 2047;
            int row = idx >> 4;
            int cc = idx & 15;
            uint32_t dst = sb + tile * AQ_BYTES + row * 256 + (((cc ^ (row & 7))) << 4);
            cp16(dst, gq[tile] + (size_t)(q0 + row) * HEAD_DIM + cc * 8);
        }
        CP_COMMIT();
    }
    attn_load_kv(sb + AKV_BASE, kf + base, vf + base, 0, tid);

    float o[16][4];
#pragma unroll
    for (int ni = 0; ni < 16; ni++)
#pragma unroll
        for (int e = 0; e < 4; e++) o[ni][e] = 0.f;
    float m0 = -1e30f, m1 = -1e30f, l0 = 0.f, l1 = 0.f;

    const int NKV = SEQ / ABKV;
    for (int it = 0; it < NKV; it++) {
        CP_WAIT(0);
        __syncthreads();
        if (it + 1 < NKV)
            attn_load_kv(sb + AKV_BASE + ((it + 1) & 1) * AKV_BUF,
                         kf + base, vf + base, (it + 1) * ABKV, tid);

        const uint32_t kfb = sb + AKV_BASE + (it & 1) * AKV_BUF;
        const uint32_t vfb = kfb + AKV_TILE;

        float s[8][4];
#pragma unroll
        for (int ni = 0; ni < 8; ni++) {
            s[ni][0] = 0.f; s[ni][1] = 0.f; s[ni][2] = 0.f; s[ni][3] = 0.f;
        }
#pragma unroll
        for (int ks = 0; ks < 8; ks++) {
            uint32_t aQh[4], aQl[4];
            const int qrow = 16 * w + (lane & 15);
            const int qcc = ks * 2 + (lane >> 4);
            const uint32_t qoff = qrow * 256 + (((qcc ^ (qrow & 7))) << 4);
            ldsm4(aQh, sb + qoff);
            ldsm4(aQl, sb + AQ_BYTES + qoff);
#pragma unroll
            for (int np = 0; np < 4; np++) {
                uint32_t bK[4];
                const int krow = np * 16 + ((lane >> 4) << 3) + (lane & 7);
                const int kcc = ks * 2 + ((lane >> 3) & 1);
                const uint32_t koff = krow * 256 + (((kcc ^ (krow & 7))) << 4);
                ldsm4(bK, kfb + koff);
                mma_f16(s[2 * np],     aQh, bK);
                mma_f16(s[2 * np],     aQl, bK);
                mma_f16(s[2 * np + 1], aQh, bK + 2);
                mma_f16(s[2 * np + 1], aQl, bK + 2);
            }
        }

        float mx0 = -1e30f, mx1 = -1e30f;
#pragma unroll
        for (int ni = 0; ni < 8; ni++) {
            mx0 = fmaxf(mx0, fmaxf(s[ni][0], s[ni][1]));
            mx1 = fmaxf(mx1, fmaxf(s[ni][2], s[ni][3]));
        }
        mx0 = fmaxf(mx0, __shfl_xor_sync(0xffffffffu, mx0, 1));
        mx0 = fmaxf(mx0, __shfl_xor_sync(0xffffffffu, mx0, 2));
        mx1 = fmaxf(mx1, __shfl_xor_sync(0xffffffffu, mx1, 1));
        mx1 = fmaxf(mx1, __shfl_xor_sync(0xffffffffu, mx1, 2));
        const float mn0 = fmaxf(m0, mx0), mn1 = fmaxf(m1, mx1);
        const float c0 = __expf(m0 - mn0), c1 = __expf(m1 - mn1);
        m0 = mn0; m1 = mn1;
        float r0s = 0.f, r1s = 0.f;
#pragma unroll
        for (int ni = 0; ni < 8; ni++) {
            s[ni][0] = __expf(s[ni][0] - mn0);
            s[ni][1] = __expf(s[ni][1] - mn0);
            s[ni][2] = __expf(s[ni][2] - mn1);
            s[ni][3] = __expf(s[ni][3] - mn1);
            r0s += s[ni][0] + s[ni][1];
            r1s += s[ni][2] + s[ni][3];
        }
        l0 = l0 * c0 + r0s;
        l1 = l1 * c1 + r1s;
#pragma unroll
        for (int ni = 0; ni < 16; ni++) {
            o[ni][0] *= c0; o[ni][1] *= c0; o[ni][2] *= c1; o[ni][3] *= c1;
        }

#pragma unroll
        for (int t = 0; t < 4; t++) {
            uint32_t aP[4];
            aP[0] = pkh2(s[2 * t][0], s[2 * t][1]);
            aP[1] = pkh2(s[2 * t][2], s[2 * t][3]);
            aP[2] = pkh2(s[2 * t + 1][0], s[2 * t + 1][1]);
            aP[3] = pkh2(s[2 * t + 1][2], s[2 * t + 1][3]);
#pragma unroll
            for (int np = 0; np < 8; np++) {
                uint32_t bV[4];
                const int vrow = t * 16 + (lane & 7) + ((lane >> 3) & 1) * 8;
                const int vcc = np * 2 + (lane >> 4);
                const uint32_t voff = vrow * 256 + (((vcc ^ (vrow & 7))) << 4);
                ldsm4t(bV, vfb + voff);
                mma_f16(o[2 * np],     aP, bV);
                mma_f16(o[2 * np + 1], aP, bV + 2);
            }
        }
        __syncthreads();
    }

    float lt0 = l0, lt1 = l1;
    lt0 += __shfl_xor_sync(0xffffffffu, lt0, 1);
    lt0 += __shfl_xor_sync(0xffffffffu, lt0, 2);
    lt1 += __shfl_xor_sync(0xffffffffu, lt1, 1);
    lt1 += __shfl_xor_sync(0xffffffffu, lt1, 2);
    const float inv0 = 1.f / lt0, inv1 = 1.f / lt1;

    const int b = bh >> 4, h = bh & 15;
    const int r = lane >> 2, cpp = (lane & 3) * 2;
    const int qr0 = q0 + 16 * w + r, qr1 = qr0 + 8;
#pragma unroll
    for (int ni = 0; ni < 16; ni++) {
        const int d = ni * 8 + cpp;
        const size_t i0 = ((size_t)(b * SEQ + qr0)) * D_MODEL + h * HEAD_DIM + d;
        const size_t i1 = ((size_t)(b * SEQ + qr1)) * D_MODEL + h * HEAD_DIM + d;
        float f0 = o[ni][0] * inv0, f1 = o[ni][1] * inv0;
        float f2 = o[ni][2] * inv1, f3 = o[ni][3] * inv1;
        *(uint32_t*)&ch[i0] = pkh2(f0, f1);
        *(uint32_t*)&cl[i0] = pkh2(hres(f0), hres(f1));
        *(uint32_t*)&ch[i1] = pkh2(f2, f3);
        *(uint32_t*)&cl[i1] = pkh2(hres(f2), hres(f3));
    }
}

// ============================================================
extern "C" void kernel_launch(void* const* d_in, const int* in_sizes, int n_in,
                              void* d_out, int out_size)
{
    const float* x  = (const float*)d_in[0];
    const float* wq = (const float*)d_in[1];
    const float* bq = (const float*)d_in[2];
    const float* wk = (const float*)d_in[3];
    const float* bk = (const float*)d_in[4];
    const float* wv = (const float*)d_in[5];
    const float* bv = (const float*)d_in[6];
    const float* wo = (const float*)d_in[7];
    const float* bo = (const float*)d_in[8];
    float* out = (float*)d_out;

    __half *xh, *xl, *wf, *ch, *cl, *qh, *ql, *kf, *vf;
    cudaGetSymbolAddress((void**)&xh, g_xh);
    cudaGetSymbolAddress((void**)&xl, g_xl);
    cudaGetSymbolAddress((void**)&wf, g_wf);
    cudaGetSymbolAddress((void**)&ch, g_ch);
    cudaGetSymbolAddress((void**)&cl, g_cl);
    cudaGetSymbolAddress((void**)&qh, g_qh);
    cudaGetSymbolAddress((void**)&ql, g_ql);
    cudaGetSymbolAddress((void**)&kf, g_kf);
    cudaGetSymbolAddress((void**)&vf, g_vf);

    const size_t WN = (size_t)D_MODEL * D_MODEL;
    const int xn4 = (int)((size_t)MROWS * D_MODEL / 4);
    const int wn4 = (int)(WN / 4);

    split_x<<<(xn4 + 255) / 256, 256>>>(x, xh, xl, xn4);
    split_w4<<<dim3((wn4 + 255) / 256, 4), 256>>>(wq, wk, wv, wo, wf, wn4);

    const int gsmem = 2 * BUFB;   // 110592
    cudaFuncSetAttribute(gemm_tc, cudaFuncAttributeMaxDynamicSharedMemorySize, gsmem);

    gemm_tc<<<dim3(3 * D_MODEL / 128, MROWS / 128), 256, gsmem>>>(
        xh, xl, wf, bq, bk, bv,
        nullptr, qh, ql, kf, vf, 1);

    cudaFuncSetAttribute(attn_tc, cudaFuncAttributeMaxDynamicSharedMemorySize, ASMEM);
    attn_tc<<<dim3(SEQ / ABQ, BATCH * NUM_HEADS), 256, ASMEM>>>(qh, ql, kf, vf, ch, cl);

    // mode-0 (output projection): bias is bo
    gemm_tc<<<dim3(D_MODEL / 128, MROWS / 128), 256, gsmem>>>(
        ch, cl, wf + 3 * WN, bo, nullptr, nullptr,
        out, nullptr, nullptr, nullptr, nullptr, 0);
}

// round 9
// speedup vs baseline: 5.2798x; 1.0008x over previous
#include <cuda_runtime.h>
#include <cuda_fp16.h>
#include <cstdint>
#include <math.h>

#define D_MODEL 2048
#define NUM_HEADS 16
#define HEAD_DIM 128
#define BATCH 2
#define SEQ 2048
#define MROWS (BATCH*SEQ)
#define GK 2048
#define QSCALE 0.0883883476483184f   // 1/sqrt(128)

// ---------------- scratch (static; no allocations allowed) ----------------
#define QKV_ELEMS ((size_t)BATCH*NUM_HEADS*SEQ*HEAD_DIM)
__device__ __align__(256) __half g_qh[QKV_ELEMS];
__device__ __align__(256) __half g_ql[QKV_ELEMS];
__device__ __align__(256) __half g_kf[QKV_ELEMS];
__device__ __align__(256) __half g_vf[QKV_ELEMS];
__device__ __align__(256) __half g_xh[(size_t)MROWS*D_MODEL];
__device__ __align__(256) __half g_xl[(size_t)MROWS*D_MODEL];
__device__ __align__(256) __half g_wf[4][(size_t)D_MODEL*D_MODEL];
__device__ __align__(256) __half g_ch[(size_t)MROWS*D_MODEL];
__device__ __align__(256) __half g_cl[(size_t)MROWS*D_MODEL];

// ---------------- helpers ----------------
__device__ __forceinline__ uint32_t smem_to_u32(const void* p) {
    uint32_t a;
    asm("{ .reg .u64 t; cvta.to.shared.u64 t, %1; cvt.u32.u64 %0, t; }" : "=r"(a) : "l"(p));
    return a;
}
__device__ __forceinline__ void ldsm4(uint32_t* r, uint32_t addr) {
    asm volatile("ldmatrix.sync.aligned.m8n8.x4.shared.b16 {%0,%1,%2,%3}, [%4];"
                 : "=r"(r[0]), "=r"(r[1]), "=r"(r[2]), "=r"(r[3]) : "r"(addr));
}
__device__ __forceinline__ void ldsm4t(uint32_t* r, uint32_t addr) {
    asm volatile("ldmatrix.sync.aligned.m8n8.x4.trans.shared.b16 {%0,%1,%2,%3}, [%4];"
                 : "=r"(r[0]), "=r"(r[1]), "=r"(r[2]), "=r"(r[3]) : "r"(addr));
}
__device__ __forceinline__ void mma_f16(float* c, const uint32_t* a, const uint32_t* b) {
    asm volatile(
        "mma.sync.aligned.m16n8k16.row.col.f32.f16.f16.f32 "
        "{%0,%1,%2,%3}, {%4,%5,%6,%7}, {%8,%9}, {%0,%1,%2,%3};"
        : "+f"(c[0]), "+f"(c[1]), "+f"(c[2]), "+f"(c[3])
        : "r"(a[0]), "r"(a[1]), "r"(a[2]), "r"(a[3]), "r"(b[0]), "r"(b[1]));
}
__device__ __forceinline__ void cp16(uint32_t saddr, const void* gaddr) {
    asm volatile("cp.async.cg.shared.global [%0], [%1], 16;" :: "r"(saddr), "l"(gaddr));
}
#define CP_COMMIT() asm volatile("cp.async.commit_group;")
#define CP_WAIT(n)  asm volatile("cp.async.wait_group %0;" :: "n"(n))

__device__ __forceinline__ uint32_t pkh2(float x0, float x1) {
    __half2 h = __floats2half2_rn(x0, x1);
    return *(uint32_t*)&h;
}
__device__ __forceinline__ float hres(float x) {
    return x - __half2float(__float2half(x));
}

// ---------------- split fp32 -> fp16 hi/lo (activations) ----------------
__global__ __launch_bounds__(256)
void split_x(const float* __restrict__ in, __half* __restrict__ hi,
             __half* __restrict__ lo, int n4)
{
    int i = blockIdx.x * blockDim.x + threadIdx.x;
    if (i >= n4) return;
    float4 v = ((const float4*)in)[i];
    ((uint32_t*)hi)[2 * i]     = pkh2(v.x, v.y);
    ((uint32_t*)hi)[2 * i + 1] = pkh2(v.z, v.w);
    ((uint32_t*)lo)[2 * i]     = pkh2(hres(v.x), hres(v.y));
    ((uint32_t*)lo)[2 * i + 1] = pkh2(hres(v.z), hres(v.w));
}

__global__ __launch_bounds__(256)
void split_w4(const float* __restrict__ w0, const float* __restrict__ w1,
              const float* __restrict__ w2, const float* __restrict__ w3,
              __half* __restrict__ hi, int n4)
{
    const float* ws[4] = {w0, w1, w2, w3};
    const float* in = ws[blockIdx.y];
    __half* h = hi + (size_t)blockIdx.y * D_MODEL * D_MODEL;
    int i = blockIdx.x * blockDim.x + threadIdx.x;
    if (i >= n4) return;
    float4 v = ((const float4*)in)[i];
    ((uint32_t*)h)[2 * i]     = pkh2(v.x, v.y);
    ((uint32_t*)h)[2 * i + 1] = pkh2(v.z, v.w);
}

// ---------------- fp16 2-term GEMM: C = (Ah+Al) @ Wf^T + bias ----------------
#define BKC 64
#define ROWB 144
#define TILE_BYTES (128*ROWB)
#define BUFB (3*TILE_BYTES)
#define NCH (GK/BKC)

__device__ __forceinline__ void load_chunk(uint32_t sbase,
                                           const __half* g0, const __half* g1,
                                           const __half* g2, int k0, int tid)
{
    const __half* gp[3] = {g0, g1, g2};
#pragma unroll
    for (int t = 0; t < 12; t++) {
        const int id = tid + t * 256;
        const int tile = id >> 10;
        const int idx = id & 1023;
        const int row = idx >> 3;
        const int c = idx & 7;
        uint32_t sa = sbase + tile * TILE_BYTES + row * ROWB + c * 16;
        const __half* ga = gp[tile] + (size_t)row * GK + k0 + c * 8;
        cp16(sa, ga);
    }
    CP_COMMIT();
}

__global__ __launch_bounds__(256, 1)
void gemm_tc(const __half* __restrict__ Ah, const __half* __restrict__ Al,
             const __half* __restrict__ Wf,
             const float* __restrict__ b0p, const float* __restrict__ b1p,
             const float* __restrict__ b2p,
             float* __restrict__ outf,
             __half* __restrict__ oqh, __half* __restrict__ oql,
             __half* __restrict__ okf, __half* __restrict__ ovf, int mode)
{
    extern __shared__ char smem[];
    const uint32_t sb = smem_to_u32(smem);
    const int tid = threadIdx.x;
    const int lane = tid & 31;
    const int wid = tid >> 5;
    const int wm = wid >> 2;
    const int wn = wid & 3;
    const int n0 = blockIdx.x * 128;
    const int m0 = blockIdx.y * 128;

    const __half* a_h = Ah + (size_t)m0 * GK;
    const __half* a_l = Al + (size_t)m0 * GK;
    const __half* b_f = Wf + (size_t)n0 * GK;

    float acc[4][4][4];
#pragma unroll
    for (int mi = 0; mi < 4; mi++)
#pragma unroll
        for (int ni = 0; ni < 4; ni++)
#pragma unroll
            for (int e = 0; e < 4; e++) acc[mi][ni][e] = 0.f;

    load_chunk(sb, a_h, a_l, b_f, 0, tid);

    const int arow = wm * 64 + (lane & 15);
    const uint32_t aoff0 = (lane >> 4) * 16;
    const int brow = wn * 32 + ((lane >> 4) << 3) + (lane & 7);
    const uint32_t boff0 = ((lane >> 3) & 1) * 16;

    // double-buffered fragments
    uint32_t ah[2][4][4], al[2][4][4], bf2[2][2][4];

    for (int ch = 0; ch < NCH; ch++) {
        CP_WAIT(0);
        __syncthreads();
        if (ch + 1 < NCH)
            load_chunk(sb + ((ch + 1) & 1) * BUFB, a_h, a_l, b_f, (ch + 1) * BKC, tid);

        const uint32_t base = sb + (ch & 1) * BUFB;
        const uint32_t aBaseH = base;
        const uint32_t aBaseL = base + TILE_BYTES;
        const uint32_t bBase  = base + 2 * TILE_BYTES;

        // load kk=0 frags
#pragma unroll
        for (int mi = 0; mi < 4; mi++) {
            ldsm4(ah[0][mi], aBaseH + (arow + mi * 16) * ROWB + aoff0);
            ldsm4(al[0][mi], aBaseL + (arow + mi * 16) * ROWB + aoff0);
        }
#pragma unroll
        for (int p = 0; p < 2; p++)
            ldsm4(bf2[0][p], bBase + (brow + p * 16) * ROWB + boff0);

#pragma unroll
        for (int kk = 0; kk < 4; kk++) {
            const int cur = kk & 1, nxt = cur ^ 1;
            if (kk < 3) {
                const uint32_t aoff = aoff0 + (kk + 1) * 32;
                const uint32_t boff = boff0 + (kk + 1) * 32;
#pragma unroll
                for (int mi = 0; mi < 4; mi++) {
                    ldsm4(ah[nxt][mi], aBaseH + (arow + mi * 16) * ROWB + aoff);
                    ldsm4(al[nxt][mi], aBaseL + (arow + mi * 16) * ROWB + aoff);
                }
#pragma unroll
                for (int p = 0; p < 2; p++)
                    ldsm4(bf2[nxt][p], bBase + (brow + p * 16) * ROWB + boff);
            }
            // hi terms: 16 independent-acc MMAs
#pragma unroll
            for (int mi = 0; mi < 4; mi++)
#pragma unroll
                for (int p = 0; p < 2; p++) {
                    mma_f16(acc[mi][2 * p],     ah[cur][mi], bf2[cur][p]);
                    mma_f16(acc[mi][2 * p + 1], ah[cur][mi], bf2[cur][p] + 2);
                }
            // lo terms
#pragma unroll
            for (int mi = 0; mi < 4; mi++)
#pragma unroll
                for (int p = 0; p < 2; p++) {
                    mma_f16(acc[mi][2 * p],     al[cur][mi], bf2[cur][p]);
                    mma_f16(acc[mi][2 * p + 1], al[cur][mi], bf2[cur][p] + 2);
                }
        }
        __syncthreads();
    }

    const int r = lane >> 2;
    const int cp = (lane & 3) * 2;
    const int mbase = m0 + wm * 64;
    const int nbase = n0 + wn * 32;

    const int proj = n0 >> 11;
    const float* bias = (mode == 0) ? b0p : (proj == 0 ? b0p : (proj == 1 ? b1p : b2p));
    const float scl = (mode == 1 && proj == 0) ? QSCALE : 1.0f;

#pragma unroll
    for (int mi = 0; mi < 4; mi++) {
#pragma unroll
        for (int ni = 0; ni < 4; ni++) {
            const int n_g = nbase + ni * 8 + cp;
            const int nb = (mode == 0) ? n_g : (n_g & 2047);
            const float b0v = bias[nb], b1v = bias[nb + 1];
            const int m0g = mbase + mi * 16 + r;
            const int m1g = m0g + 8;
            float v0x = (acc[mi][ni][0] + b0v) * scl;
            float v0y = (acc[mi][ni][1] + b1v) * scl;
            float v1x = (acc[mi][ni][2] + b0v) * scl;
            float v1y = (acc[mi][ni][3] + b1v) * scl;
            if (mode == 0) {
                float2 v0 = {v0x, v0y}, v1 = {v1x, v1y};
                *(float2*)&outf[(size_t)m0g * D_MODEL + n_g] = v0;
                *(float2*)&outf[(size_t)m1g * D_MODEL + n_g] = v1;
            } else {
                const int h = (n_g >> 7) & 15;
                const int d = n_g & 127;
                const int b0i = m0g >> 11, s0 = m0g & 2047;
                const int b1i = m1g >> 11, s1 = m1g & 2047;
                const size_t i0 = (((size_t)(b0i * NUM_HEADS + h) * SEQ + s0) * HEAD_DIM) + d;
                const size_t i1 = (((size_t)(b1i * NUM_HEADS + h) * SEQ + s1) * HEAD_DIM) + d;
                if (proj == 0) {
                    *(uint32_t*)&oqh[i0] = pkh2(v0x, v0y);
                    *(uint32_t*)&oql[i0] = pkh2(hres(v0x), hres(v0y));
                    *(uint32_t*)&oqh[i1] = pkh2(v1x, v1y);
                    *(uint32_t*)&oql[i1] = pkh2(hres(v1x), hres(v1y));
                } else if (proj == 1) {
                    *(uint32_t*)&okf[i0] = pkh2(v0x, v0y);
                    *(uint32_t*)&okf[i1] = pkh2(v1x, v1y);
                } else {
                    *(uint32_t*)&ovf[i0] = pkh2(v0x, v0y);
                    *(uint32_t*)&ovf[i1] = pkh2(v1x, v1y);
                }
            }
        }
    }
}

// ============================================================
// Flash attention: QK^T = (Qh+Ql)·Kf (2-term fp16); PV single fp16.
// ============================================================
#define ABQ 128
#define ABKV 64
#define AQ_BYTES 32768
#define AKV_TILE 16384
#define AKV_BUF  (2*AKV_TILE)
#define AKV_BASE (2*AQ_BYTES)
#define ASMEM (AKV_BASE + 2*AKV_BUF)

__device__ __forceinline__ void attn_load_kv(uint32_t sbuf,
    const __half* kf_, const __half* vf_, int kv0, int tid)
{
    const __half* gp[2] = {kf_, vf_};
#pragma unroll
    for (int i = 0; i < 8; i++) {
        int id = i * 256 + tid;
        int tile = id >> 10;
        int idx = id & 1023;
        int row = idx >> 4;
        int cc = idx & 15;
        uint32_t dst = sbuf + tile * AKV_TILE + row * 256 + (((cc ^ (row & 7))) << 4);
        cp16(dst, gp[tile] + (size_t)(kv0 + row) * HEAD_DIM + cc * 8);
    }
    CP_COMMIT();
}

__global__ __launch_bounds__(256, 1)
void attn_tc(const __half* __restrict__ qh, const __half* __restrict__ ql,
             const __half* __restrict__ kf, const __half* __restrict__ vf,
             __half* __restrict__ ch, __half* __restrict__ cl)
{
    extern __shared__ char smem[];
    const uint32_t sb = smem_to_u32(smem);
    const int tid = threadIdx.x;
    const int lane = tid & 31;
    const int w = tid >> 5;
    const int bh = blockIdx.y;
    const int q0 = blockIdx.x * ABQ;
    const size_t base = (size_t)bh * SEQ * HEAD_DIM;

    {
        const __half* gq[2] = {qh + base, ql + base};
#pragma unroll
        for (int i = 0; i < 16; i++) {
            int id = i * 256 + tid;
            int tile = id >> 11;
            int idx = id & 2047;
            int row = idx >> 4;
            int cc = idx & 15;
            uint32_t dst = sb + tile * AQ_BYTES + row * 256 + (((cc ^ (row & 7))) << 4);
            cp16(dst, gq[tile] + (size_t)(q0 + row) * HEAD_DIM + cc * 8);
        }
        CP_COMMIT();
    }
    attn_load_kv(sb + AKV_BASE, kf + base, vf + base, 0, tid);

    float o[16][4];
#pragma unroll
    for (int ni = 0; ni < 16; ni++)
#pragma unroll
        for (int e = 0; e < 4; e++) o[ni][e] = 0.f;
    float m0 = -1e30f, m1 = -1e30f, l0 = 0.f, l1 = 0.f;

    const int NKV = SEQ / ABKV;
    for (int it = 0; it < NKV; it++) {
        CP_WAIT(0);
        __syncthreads();
        if (it + 1 < NKV)
            attn_load_kv(sb + AKV_BASE + ((it + 1) & 1) * AKV_BUF,
                         kf + base, vf + base, (it + 1) * ABKV, tid);

        const uint32_t kfb = sb + AKV_BASE + (it & 1) * AKV_BUF;
        const uint32_t vfb = kfb + AKV_TILE;

        float s[8][4];
#pragma unroll
        for (int ni = 0; ni < 8; ni++) {
            s[ni][0] = 0.f; s[ni][1] = 0.f; s[ni][2] = 0.f; s[ni][3] = 0.f;
        }
#pragma unroll
        for (int ks = 0; ks < 8; ks++) {
            uint32_t aQh[4], aQl[4], bK[4][4];
            const int qrow = 16 * w + (lane & 15);
            const int qcc = ks * 2 + (lane >> 4);
            const uint32_t qoff = qrow * 256 + (((qcc ^ (qrow & 7))) << 4);
            ldsm4(aQh, sb + qoff);
            ldsm4(aQl, sb + AQ_BYTES + qoff);
            const int krow0 = ((lane >> 4) << 3) + (lane & 7);
            const int kcc = ks * 2 + ((lane >> 3) & 1);
#pragma unroll
            for (int np = 0; np < 4; np++) {
                const int krow = np * 16 + krow0;
                ldsm4(bK[np], kfb + krow * 256 + (((kcc ^ (krow & 7))) << 4));
            }
            // hi terms: 8 independent MMAs
#pragma unroll
            for (int np = 0; np < 4; np++) {
                mma_f16(s[2 * np],     aQh, bK[np]);
                mma_f16(s[2 * np + 1], aQh, bK[np] + 2);
            }
            // lo terms
#pragma unroll
            for (int np = 0; np < 4; np++) {
                mma_f16(s[2 * np],     aQl, bK[np]);
                mma_f16(s[2 * np + 1], aQl, bK[np] + 2);
            }
        }

        float mx0 = -1e30f, mx1 = -1e30f;
#pragma unroll
        for (int ni = 0; ni < 8; ni++) {
            mx0 = fmaxf(mx0, fmaxf(s[ni][0], s[ni][1]));
            mx1 = fmaxf(mx1, fmaxf(s[ni][2], s[ni][3]));
        }
        mx0 = fmaxf(mx0, __shfl_xor_sync(0xffffffffu, mx0, 1));
        mx0 = fmaxf(mx0, __shfl_xor_sync(0xffffffffu, mx0, 2));
        mx1 = fmaxf(mx1, __shfl_xor_sync(0xffffffffu, mx1, 1));
        mx1 = fmaxf(mx1, __shfl_xor_sync(0xffffffffu, mx1, 2));
        const float mn0 = fmaxf(m0, mx0), mn1 = fmaxf(m1, mx1);
        const float c0 = __expf(m0 - mn0), c1 = __expf(m1 - mn1);
        m0 = mn0; m1 = mn1;
        float r0s = 0.f, r1s = 0.f;
#pragma unroll
        for (int ni = 0; ni < 8; ni++) {
            s[ni][0] = __expf(s[ni][0] - mn0);
            s[ni][1] = __expf(s[ni][1] - mn0);
            s[ni][2] = __expf(s[ni][2] - mn1);
            s[ni][3] = __expf(s[ni][3] - mn1);
            r0s += s[ni][0] + s[ni][1];
            r1s += s[ni][2] + s[ni][3];
        }
        l0 = l0 * c0 + r0s;
        l1 = l1 * c1 + r1s;
#pragma unroll
        for (int ni = 0; ni < 16; ni++) {
            o[ni][0] *= c0; o[ni][1] *= c0; o[ni][2] *= c1; o[ni][3] *= c1;
        }

#pragma unroll
        for (int t = 0; t < 4; t++) {
            uint32_t aP[4];
            aP[0] = pkh2(s[2 * t][0], s[2 * t][1]);
            aP[1] = pkh2(s[2 * t][2], s[2 * t][3]);
            aP[2] = pkh2(s[2 * t + 1][0], s[2 * t + 1][1]);
            aP[3] = pkh2(s[2 * t + 1][2], s[2 * t + 1][3]);
            const int vrow = t * 16 + (lane & 7) + ((lane >> 3) & 1) * 8;
#pragma unroll
            for (int half = 0; half < 2; half++) {
                uint32_t bV[4][4];
#pragma unroll
                for (int j = 0; j < 4; j++) {
                    const int np = half * 4 + j;
                    const int vcc = np * 2 + (lane >> 4);
                    ldsm4t(bV[j], vfb + vrow * 256 + (((vcc ^ (vrow & 7))) << 4));
                }
#pragma unroll
                for (int j = 0; j < 4; j++) {
                    const int np = half * 4 + j;
                    mma_f16(o[2 * np],     aP, bV[j]);
                    mma_f16(o[2 * np + 1], aP, bV[j] + 2);
                }
            }
        }
        __syncthreads();
    }

    float lt0 = l0, lt1 = l1;
    lt0 += __shfl_xor_sync(0xffffffffu, lt0, 1);
    lt0 += __shfl_xor_sync(0xffffffffu, lt0, 2);
    lt1 += __shfl_xor_sync(0xffffffffu, lt1, 1);
    lt1 += __shfl_xor_sync(0xffffffffu, lt1, 2);
    const float inv0 = 1.f / lt0, inv1 = 1.f / lt1;

    const int b = bh >> 4, h = bh & 15;
    const int r = lane >> 2, cpp = (lane & 3) * 2;
    const int qr0 = q0 + 16 * w + r, qr1 = qr0 + 8;
#pragma unroll
    for (int ni = 0; ni < 16; ni++) {
        const int d = ni * 8 + cpp;
        const size_t i0 = ((size_t)(b * SEQ + qr0)) * D_MODEL + h * HEAD_DIM + d;
        const size_t i1 = ((size_t)(b * SEQ + qr1)) * D_MODEL + h * HEAD_DIM + d;
        float f0 = o[ni][0] * inv0, f1 = o[ni][1] * inv0;
        float f2 = o[ni][2] * inv1, f3 = o[ni][3] * inv1;
        *(uint32_t*)&ch[i0] = pkh2(f0, f1);
        *(uint32_t*)&cl[i0] = pkh2(hres(f0), hres(f1));
        *(uint32_t*)&ch[i1] = pkh2(f2, f3);
        *(uint32_t*)&cl[i1] = pkh2(hres(f2), hres(f3));
    }
}

// ============================================================
extern "C" void kernel_launch(void* const* d_in, const int* in_sizes, int n_in,
                              void* d_out, int out_size)
{
    const float* x  = (const float*)d_in[0];
    const float* wq = (const float*)d_in[1];
    const float* bq = (const float*)d_in[2];
    const float* wk = (const float*)d_in[3];
    const float* bk = (const float*)d_in[4];
    const float* wv = (const float*)d_in[5];
    const float* bv = (const float*)d_in[6];
    const float* wo = (const float*)d_in[7];
    const float* bo = (const float*)d_in[8];
    float* out = (float*)d_out;

    __half *xh, *xl, *wf, *ch, *cl, *qh, *ql, *kf, *vf;
    cudaGetSymbolAddress((void**)&xh, g_xh);
    cudaGetSymbolAddress((void**)&xl, g_xl);
    cudaGetSymbolAddress((void**)&wf, g_wf);
    cudaGetSymbolAddress((void**)&ch, g_ch);
    cudaGetSymbolAddress((void**)&cl, g_cl);
    cudaGetSymbolAddress((void**)&qh, g_qh);
    cudaGetSymbolAddress((void**)&ql, g_ql);
    cudaGetSymbolAddress((void**)&kf, g_kf);
    cudaGetSymbolAddress((void**)&vf, g_vf);

    const size_t WN = (size_t)D_MODEL * D_MODEL;
    const int xn4 = (int)((size_t)MROWS * D_MODEL / 4);
    const int wn4 = (int)(WN / 4);

    split_x<<<(xn4 + 255) / 256, 256>>>(x, xh, xl, xn4);
    split_w4<<<dim3((wn4 + 255) / 256, 4), 256>>>(wq, wk, wv, wo, wf, wn4);

    const int gsmem = 2 * BUFB;
    cudaFuncSetAttribute(gemm_tc, cudaFuncAttributeMaxDynamicSharedMemorySize, gsmem);

    gemm_tc<<<dim3(3 * D_MODEL / 128, MROWS / 128), 256, gsmem>>>(
        xh, xl, wf, bq, bk, bv,
        nullptr, qh, ql, kf, vf, 1);

    cudaFuncSetAttribute(attn_tc, cudaFuncAttributeMaxDynamicSharedMemorySize, ASMEM);
    attn_tc<<<dim3(SEQ / ABQ, BATCH * NUM_HEADS), 256, ASMEM>>>(qh, ql, kf, vf, ch, cl);

    // mode-0 (output projection): bias is bo
    gemm_tc<<<dim3(D_MODEL / 128, MROWS / 128), 256, gsmem>>>(
        ch, cl, wf + 3 * WN, bo, nullptr, nullptr,
        out, nullptr, nullptr, nullptr, nullptr, 0);
}